// round 1
// baseline (speedup 1.0000x reference)
#include <cuda_runtime.h>
#include <math.h>

// ---------------- static config ----------------
#define Bq   4
#define Hq   256
#define Wq   256
#define Cq   96
#define WSz  8
#define SSz  4
#define NHq  3
#define Nq   64           // tokens per window
#define NWq  1024         // windows per image
#define HDq  32
#define MLPH 384
#define TOKENS (Bq*Hq*Wq) // 262144
static __device__ float g_x2[(size_t)TOKENS * Cq];   // scratch: x + attn branch

#define SCALEq 0.17677669529663687f   // 32^-0.5
#define EPSq   1e-5f

// ---------------- shared layouts ----------------
// K_A smem (floats):
//  h_s  : 64*96            = 6144
//  w_s  : 96*97            = 9312   (attn_s 64*64=4096 aliases its head)
//  q_s  : 64*32            = 2048
//  k_s  : 64*33            = 2112
//  v_s  : 64*32            = 2048
//  o_s  : 64*96            = 6144
#define A_SMEM_FLOATS (6144 + 9312 + 2048 + 2112 + 2048 + 6144)
// K_M smem (floats): x_s 6144, ln_s 6144, w_s 9312, h1_s 6144
#define M_SMEM_FLOATS (6144 + 6144 + 9312 + 6144)

// ================= Attention kernel: one CTA per window =================
__global__ __launch_bounds__(256, 2)
void swin_attn_kernel(const float* __restrict__ x,
                      const float* __restrict__ g1, const float* __restrict__ b1,
                      const float* __restrict__ qkv_w, const float* __restrict__ qkv_b,
                      const float* __restrict__ rpb,
                      const float* __restrict__ proj_w, const float* __restrict__ proj_b,
                      const float* __restrict__ attn_mask,
                      const int*   __restrict__ rel_index,
                      float* __restrict__ x2)
{
    extern __shared__ float smem[];
    float* h_s   = smem;                 // 64*96
    float* w_s   = h_s + 6144;           // 96*97
    float* attn_s= w_s;                  // alias (64*64 <= 96*97)
    float* q_s   = w_s + 9312;           // 64*32
    float* k_s   = q_s + 2048;           // 64*33
    float* v_s   = k_s + 2112;           // 64*32
    float* o_s   = v_s + 2048;           // 64*96

    const int tid  = threadIdx.x;
    const int lane = tid & 31;
    const int warp = tid >> 5;
    const int w    = blockIdx.x;
    const int b    = w >> 10;
    const int wrem = w & 1023;
    const int wy   = wrem >> 5;
    const int wx   = wrem & 31;

    // ---- stage 0: gather (cyclic shift + window partition) + LayerNorm1 ----
    #pragma unroll
    for (int r = 0; r < 8; r++) {
        const int t  = warp * 8 + r;
        const int iy = t >> 3, ix = t & 7;
        const int yy = (wy * 8 + iy + SSz) & 255;
        const int xx = (wx * 8 + ix + SSz) & 255;
        const int tok = b * 65536 + yy * 256 + xx;
        const float* row = x + (size_t)tok * Cq;
        float v0 = row[lane], v1 = row[lane + 32], v2 = row[lane + 64];
        float s  = v0 + v1 + v2;
        float ss = v0 * v0 + v1 * v1 + v2 * v2;
        #pragma unroll
        for (int o = 16; o; o >>= 1) {
            s  += __shfl_xor_sync(0xffffffffu, s,  o);
            ss += __shfl_xor_sync(0xffffffffu, ss, o);
        }
        const float mu  = s * (1.0f / 96.0f);
        const float var = ss * (1.0f / 96.0f) - mu * mu;
        const float inv = rsqrtf(var + EPSq);
        h_s[t * 96 + lane]      = (v0 - mu) * inv * g1[lane]      + b1[lane];
        h_s[t * 96 + lane + 32] = (v1 - mu) * inv * g1[lane + 32] + b1[lane + 32];
        h_s[t * 96 + lane + 64] = (v2 - mu) * inv * g1[lane + 64] + b1[lane + 64];
    }
    __syncthreads();

    const int d  = tid & 31;
    const int ty = tid >> 5;

    // ---- per-head loop ----
    for (int hh = 0; hh < NHq; hh++) {
        // stage a: stage qkv weight slice for this head into smem (96 rows x 96 cols)
        for (int idx = tid; idx < 96 * 96; idx += 256) {
            const int rr = idx / 96, c = idx - rr * 96;
            const int grow = (rr >> 5) * 96 + hh * 32 + (rr & 31); // q rows, k rows, v rows
            w_s[rr * 97 + c] = qkv_w[grow * 96 + c];
        }
        __syncthreads();

        // stage b: q,k,v = h @ W^T (64x32 each), 8 independent accum chains/thread
        {
            float aq[8], ak[8], av[8];
            #pragma unroll
            for (int r = 0; r < 8; r++) { aq[r] = 0.f; ak[r] = 0.f; av[r] = 0.f; }
            const float* wqp = &w_s[d * 97];
            const float* wkp = &w_s[(32 + d) * 97];
            const float* wvp = &w_s[(64 + d) * 97];
            const float* hb  = &h_s[(ty * 8) * 96];
            #pragma unroll 4
            for (int c = 0; c < 96; c++) {
                const float fq = wqp[c], fk = wkp[c], fv = wvp[c];
                #pragma unroll
                for (int r = 0; r < 8; r++) {
                    const float hv = hb[r * 96 + c];
                    aq[r] = fmaf(hv, fq, aq[r]);
                    ak[r] = fmaf(hv, fk, ak[r]);
                    av[r] = fmaf(hv, fv, av[r]);
                }
            }
            const float bq = qkv_b[hh * 32 + d];
            const float bk = qkv_b[96 + hh * 32 + d];
            const float bv = qkv_b[192 + hh * 32 + d];
            #pragma unroll
            for (int r = 0; r < 8; r++) {
                const int t = ty * 8 + r;
                q_s[t * 32 + d] = (aq[r] + bq) * SCALEq;
                k_s[t * 33 + d] = ak[r] + bk;
                v_s[t * 32 + d] = av[r] + bv;
            }
        }
        __syncthreads();

        // stage c: scores = q @ k^T + bias + mask  (writes alias w_s; readers done)
        {
            const int j  = tid & 63;
            const int ib = tid >> 6;    // 0..3, rows i = ib + 4*r
            float acc[16];
            #pragma unroll
            for (int r = 0; r < 16; r++) acc[r] = 0.f;
            #pragma unroll 4
            for (int dd = 0; dd < 32; dd++) {
                const float kv = k_s[j * 33 + dd];
                #pragma unroll
                for (int r = 0; r < 16; r++)
                    acc[r] = fmaf(q_s[(ib + 4 * r) * 32 + dd], kv, acc[r]);
            }
            const float* mrow = attn_mask + (size_t)wrem * 4096;
            #pragma unroll
            for (int r = 0; r < 16; r++) {
                const int i  = ib + 4 * r;
                const int ri = rel_index[i * 64 + j];
                attn_s[i * 64 + j] = acc[r] + rpb[ri * 3 + hh] + mrow[i * 64 + j];
            }
        }
        __syncthreads();

        // stage d: row softmax (one warp handles 8 rows)
        #pragma unroll
        for (int r = 0; r < 8; r++) {
            const int i = warp * 8 + r;
            float a0 = attn_s[i * 64 + lane];
            float a1 = attn_s[i * 64 + lane + 32];
            float m = fmaxf(a0, a1);
            #pragma unroll
            for (int o = 16; o; o >>= 1) m = fmaxf(m, __shfl_xor_sync(0xffffffffu, m, o));
            const float e0 = __expf(a0 - m), e1 = __expf(a1 - m);
            float s = e0 + e1;
            #pragma unroll
            for (int o = 16; o; o >>= 1) s += __shfl_xor_sync(0xffffffffu, s, o);
            const float inv = 1.0f / s;
            attn_s[i * 64 + lane]      = e0 * inv;
            attn_s[i * 64 + lane + 32] = e1 * inv;
        }
        __syncthreads();

        // stage e: o = attn @ v  -> o_s[:, hh*32 + d]
        {
            float acc[8];
            #pragma unroll
            for (int r = 0; r < 8; r++) acc[r] = 0.f;
            #pragma unroll 4
            for (int j = 0; j < 64; j++) {
                const float vv = v_s[j * 32 + d];
                #pragma unroll
                for (int r = 0; r < 8; r++)
                    acc[r] = fmaf(attn_s[(ty * 8 + r) * 64 + j], vv, acc[r]);
            }
            #pragma unroll
            for (int r = 0; r < 8; r++)
                o_s[(ty * 8 + r) * 96 + hh * 32 + d] = acc[r];
        }
        __syncthreads();
    }

    // ---- proj + residual scatter ----
    for (int idx = tid; idx < 96 * 96; idx += 256)
        w_s[(idx / 96) * 97 + (idx % 96)] = proj_w[idx];
    __syncthreads();

    #pragma unroll
    for (int ch = 0; ch < 3; ch++) {
        const int c = ch * 32 + d;
        float acc[8];
        #pragma unroll
        for (int r = 0; r < 8; r++) acc[r] = 0.f;
        const float* wrow = &w_s[c * 97];
        #pragma unroll 4
        for (int k = 0; k < 96; k++) {
            const float wv = wrow[k];
            #pragma unroll
            for (int r = 0; r < 8; r++)
                acc[r] = fmaf(o_s[(ty * 8 + r) * 96 + k], wv, acc[r]);
        }
        const float pb = proj_b[c];
        #pragma unroll
        for (int r = 0; r < 8; r++) {
            const int t  = ty * 8 + r;
            const int iy = t >> 3, ix = t & 7;
            const int yy = (wy * 8 + iy + SSz) & 255;
            const int xx = (wx * 8 + ix + SSz) & 255;
            const int tok = b * 65536 + yy * 256 + xx;
            x2[(size_t)tok * Cq + c] = x[(size_t)tok * Cq + c] + acc[r] + pb;
        }
    }
}

// ================= MLP kernel: 64 consecutive tokens per CTA =================
__global__ __launch_bounds__(256, 2)
void swin_mlp_kernel(const float* __restrict__ x2,
                     const float* __restrict__ g2, const float* __restrict__ b2,
                     const float* __restrict__ fc1_w, const float* __restrict__ fc1_b,
                     const float* __restrict__ fc2_w, const float* __restrict__ fc2_b,
                     float* __restrict__ out)
{
    extern __shared__ float smem[];
    float* x_s  = smem;            // 64*96
    float* ln_s = x_s + 6144;      // 64*96
    float* w_s  = ln_s + 6144;     // 96*97
    float* h1_s = w_s + 9312;      // 64*96

    const int tid  = threadIdx.x;
    const int lane = tid & 31;
    const int warp = tid >> 5;
    const size_t t0 = (size_t)blockIdx.x * 64;

    // ---- LayerNorm2 ----
    #pragma unroll
    for (int r = 0; r < 8; r++) {
        const int t = warp * 8 + r;
        const float* row = x2 + (t0 + t) * Cq;
        float v0 = row[lane], v1 = row[lane + 32], v2 = row[lane + 64];
        float s  = v0 + v1 + v2;
        float ss = v0 * v0 + v1 * v1 + v2 * v2;
        #pragma unroll
        for (int o = 16; o; o >>= 1) {
            s  += __shfl_xor_sync(0xffffffffu, s,  o);
            ss += __shfl_xor_sync(0xffffffffu, ss, o);
        }
        const float mu  = s * (1.0f / 96.0f);
        const float var = ss * (1.0f / 96.0f) - mu * mu;
        const float inv = rsqrtf(var + EPSq);
        x_s[t * 96 + lane]      = v0;
        x_s[t * 96 + lane + 32] = v1;
        x_s[t * 96 + lane + 64] = v2;
        ln_s[t * 96 + lane]      = (v0 - mu) * inv * g2[lane]      + b2[lane];
        ln_s[t * 96 + lane + 32] = (v1 - mu) * inv * g2[lane + 32] + b2[lane + 32];
        ln_s[t * 96 + lane + 64] = (v2 - mu) * inv * g2[lane + 64] + b2[lane + 64];
    }
    __syncthreads();

    const int d  = tid & 31;
    const int ty = tid >> 5;

    float acc[3][8];
    #pragma unroll
    for (int ch = 0; ch < 3; ch++)
        #pragma unroll
        for (int r = 0; r < 8; r++) acc[ch][r] = 0.f;

    for (int jc = 0; jc < 4; jc++) {
        // stage fc1 weights chunk: rows jc*96 .. jc*96+95
        for (int idx = tid; idx < 96 * 96; idx += 256) {
            const int j = idx / 96, c = idx - j * 96;
            w_s[j * 97 + c] = fc1_w[(jc * 96 + j) * 96 + c];
        }
        __syncthreads();

        // h1 chunk = gelu(ln @ W1^T + b1)
        #pragma unroll
        for (int ch = 0; ch < 3; ch++) {
            const int j = ch * 32 + d;
            float a[8];
            #pragma unroll
            for (int r = 0; r < 8; r++) a[r] = 0.f;
            const float* wr = &w_s[j * 97];
            #pragma unroll 4
            for (int c = 0; c < 96; c++) {
                const float wv = wr[c];
                #pragma unroll
                for (int r = 0; r < 8; r++)
                    a[r] = fmaf(ln_s[(ty * 8 + r) * 96 + c], wv, a[r]);
            }
            const float bb = fc1_b[jc * 96 + j];
            #pragma unroll
            for (int r = 0; r < 8; r++) {
                const float v = a[r] + bb;
                h1_s[(ty * 8 + r) * 96 + j] = 0.5f * v * (1.0f + erff(v * 0.70710678118654752f));
            }
        }
        __syncthreads();

        // stage fc2 weight chunk: fc2_w[c][jc*96 + j]
        for (int idx = tid; idx < 96 * 96; idx += 256) {
            const int c = idx / 96, j = idx - c * 96;
            w_s[c * 97 + j] = fc2_w[c * MLPH + jc * 96 + j];
        }
        __syncthreads();

        // accumulate out += h1chunk @ W2chunk^T
        #pragma unroll
        for (int ch = 0; ch < 3; ch++) {
            const int c = ch * 32 + d;
            const float* wr = &w_s[c * 97];
            #pragma unroll 4
            for (int j = 0; j < 96; j++) {
                const float wv = wr[j];
                #pragma unroll
                for (int r = 0; r < 8; r++)
                    acc[ch][r] = fmaf(h1_s[(ty * 8 + r) * 96 + j], wv, acc[ch][r]);
            }
        }
        __syncthreads();
    }

    // ---- residual + store ----
    #pragma unroll
    for (int ch = 0; ch < 3; ch++) {
        const int c = ch * 32 + d;
        const float bb = fc2_b[c];
        #pragma unroll
        for (int r = 0; r < 8; r++) {
            const int t = ty * 8 + r;
            out[(t0 + t) * Cq + c] = x_s[t * 96 + c] + acc[ch][r] + bb;
        }
    }
}

// ================= launch =================
extern "C" void kernel_launch(void* const* d_in, const int* in_sizes, int n_in,
                              void* d_out, int out_size)
{
    const float* x        = (const float*)d_in[0];
    const float* g1       = (const float*)d_in[1];
    const float* b1       = (const float*)d_in[2];
    const float* qkv_w    = (const float*)d_in[3];
    const float* qkv_b    = (const float*)d_in[4];
    const float* rpb      = (const float*)d_in[5];
    const float* proj_w   = (const float*)d_in[6];
    const float* proj_b   = (const float*)d_in[7];
    const float* g2       = (const float*)d_in[8];
    const float* b2       = (const float*)d_in[9];
    const float* fc1_w    = (const float*)d_in[10];
    const float* fc1_b    = (const float*)d_in[11];
    const float* fc2_w    = (const float*)d_in[12];
    const float* fc2_b    = (const float*)d_in[13];
    const float* attn_mask= (const float*)d_in[14];
    const int*   rel_index= (const int*)  d_in[15];
    float* out = (float*)d_out;

    const size_t a_smem = A_SMEM_FLOATS * sizeof(float);
    const size_t m_smem = M_SMEM_FLOATS * sizeof(float);
    cudaFuncSetAttribute(swin_attn_kernel, cudaFuncAttributeMaxDynamicSharedMemorySize, (int)a_smem);
    cudaFuncSetAttribute(swin_mlp_kernel,  cudaFuncAttributeMaxDynamicSharedMemorySize, (int)m_smem);

    float* x2;
    cudaGetSymbolAddress((void**)&x2, g_x2);

    swin_attn_kernel<<<Bq * NWq, 256, a_smem>>>(x, g1, b1, qkv_w, qkv_b, rpb,
                                                proj_w, proj_b, attn_mask, rel_index, x2);
    swin_mlp_kernel<<<TOKENS / 64, 256, m_smem>>>(x2, g2, b2, fc1_w, fc1_b,
                                                  fc2_w, fc2_b, out);
}

// round 2
// speedup vs baseline: 1.2647x; 1.2647x over previous
#include <cuda_runtime.h>
#include <math.h>

// ---------------- static config ----------------
#define Bq   4
#define Hq   256
#define Wq   256
#define Cq   96
#define WSz  8
#define SSz  4
#define NHq  3
#define Nq   64
#define NWq  1024
#define HDq  32
#define MLPH 384
#define TOKENS (Bq*Hq*Wq)
static __device__ float g_x2[(size_t)TOKENS * Cq];

#define SCALEq 0.17677669529663687f
#define EPSq   1e-5f

// ---------------- shared layouts (floats) ----------------
// K_A: h_s 64*96=6144 | w_s 96*100=9600 (attn_s 64*64 aliases) | q_s 64*32=2048
//      k_s 64*36=2304 | v_s (transposed) 32*68=2176 | o_s 64*96=6144
#define A_SMEM_FLOATS (6144 + 9600 + 2048 + 2304 + 2176 + 6144)
// K_M: x_s 6144 | ln_s 6144 | w_s 96*100=9600 | h1_s 6144
#define M_SMEM_FLOATS (6144 + 6144 + 9600 + 6144)

__device__ __forceinline__ float4 ld4(const float* p) { return *(const float4*)p; }

// ================= Attention kernel: one CTA per window =================
__global__ __launch_bounds__(256, 2)
void swin_attn_kernel(const float* __restrict__ x,
                      const float* __restrict__ g1, const float* __restrict__ b1,
                      const float* __restrict__ qkv_w, const float* __restrict__ qkv_b,
                      const float* __restrict__ rpb,
                      const float* __restrict__ proj_w, const float* __restrict__ proj_b,
                      const float* __restrict__ attn_mask,
                      const int*   __restrict__ rel_index,
                      float* __restrict__ x2)
{
    extern __shared__ float smem[];
    float* h_s    = smem;                 // [64][96]
    float* w_s    = h_s + 6144;           // [96][100]
    float* attn_s = w_s;                  // alias [64][64]
    float* q_s    = w_s + 9600;           // [64][32]
    float* k_s    = q_s + 2048;           // [64][36]
    float* v_s    = k_s + 2304;           // [32][68]  (v transposed: [d][t])
    float* o_s    = v_s + 2176;           // [64][96]

    const int tid  = threadIdx.x;
    const int lane = tid & 31;
    const int warp = tid >> 5;
    const int w    = blockIdx.x;
    const int b    = w >> 10;
    const int wrem = w & 1023;
    const int wy   = wrem >> 5;
    const int wx   = wrem & 31;

    // ---- stage 0: gather (cyclic shift + window partition) + LayerNorm1 ----
    #pragma unroll
    for (int r = 0; r < 8; r++) {
        const int t  = warp * 8 + r;
        const int iy = t >> 3, ix = t & 7;
        const int yy = (wy * 8 + iy + SSz) & 255;
        const int xx = (wx * 8 + ix + SSz) & 255;
        const int tok = b * 65536 + yy * 256 + xx;
        const float* row = x + (size_t)tok * Cq;
        float v0 = row[lane], v1 = row[lane + 32], v2 = row[lane + 64];
        float s  = v0 + v1 + v2;
        float ss = v0 * v0 + v1 * v1 + v2 * v2;
        #pragma unroll
        for (int o = 16; o; o >>= 1) {
            s  += __shfl_xor_sync(0xffffffffu, s,  o);
            ss += __shfl_xor_sync(0xffffffffu, ss, o);
        }
        const float mu  = s * (1.0f / 96.0f);
        const float var = ss * (1.0f / 96.0f) - mu * mu;
        const float inv = rsqrtf(var + EPSq);
        h_s[t * 96 + lane]      = (v0 - mu) * inv * g1[lane]      + b1[lane];
        h_s[t * 96 + lane + 32] = (v1 - mu) * inv * g1[lane + 32] + b1[lane + 32];
        h_s[t * 96 + lane + 64] = (v2 - mu) * inv * g1[lane + 64] + b1[lane + 64];
    }
    __syncthreads();

    const int d  = tid & 31;
    const int ty = tid >> 5;

    for (int hh = 0; hh < NHq; hh++) {
        // ---- stage a: stage head's qkv weight slice [96][96] -> w_s ----
        for (int idx = tid; idx < 96 * 96; idx += 256) {
            const int rr = idx / 96, c = idx - rr * 96;
            const int grow = (rr >> 5) * 96 + hh * 32 + (rr & 31);
            w_s[rr * 100 + c] = qkv_w[grow * 96 + c];
        }
        __syncthreads();

        // ---- stage b: q,k,v = h @ W^T  (8 rows x 3 outputs per thread) ----
        {
            float aq[8], ak[8], av[8];
            #pragma unroll
            for (int r = 0; r < 8; r++) { aq[r] = 0.f; ak[r] = 0.f; av[r] = 0.f; }
            const float* wq = &w_s[d * 100];
            const float* wk = &w_s[(32 + d) * 100];
            const float* wv = &w_s[(64 + d) * 100];
            const float* hb = &h_s[(ty * 8) * 96];
            #pragma unroll
            for (int c4 = 0; c4 < 96; c4 += 4) {
                const float4 fq = ld4(wq + c4);
                const float4 fk = ld4(wk + c4);
                const float4 fv = ld4(wv + c4);
                #pragma unroll
                for (int r = 0; r < 8; r++) {
                    const float4 hv = ld4(hb + r * 96 + c4);
                    aq[r] = fmaf(hv.x, fq.x, fmaf(hv.y, fq.y, fmaf(hv.z, fq.z, fmaf(hv.w, fq.w, aq[r]))));
                    ak[r] = fmaf(hv.x, fk.x, fmaf(hv.y, fk.y, fmaf(hv.z, fk.z, fmaf(hv.w, fk.w, ak[r]))));
                    av[r] = fmaf(hv.x, fv.x, fmaf(hv.y, fv.y, fmaf(hv.z, fv.z, fmaf(hv.w, fv.w, av[r]))));
                }
            }
            const float bq = qkv_b[hh * 32 + d];
            const float bk = qkv_b[96 + hh * 32 + d];
            const float bv = qkv_b[192 + hh * 32 + d];
            #pragma unroll
            for (int r = 0; r < 8; r++) {
                const int t = ty * 8 + r;
                q_s[t * 32 + d] = (aq[r] + bq) * SCALEq;
                k_s[t * 36 + d] = ak[r] + bk;
                v_s[d * 68 + t] = av[r] + bv;   // transposed
            }
        }
        __syncthreads();

        // ---- stage c: scores = q @ k^T + bias + mask ----
        {
            const int j  = tid & 63;
            const int ib = tid >> 6;
            float acc[16];
            #pragma unroll
            for (int r = 0; r < 16; r++) acc[r] = 0.f;
            const float* kp = &k_s[j * 36];
            #pragma unroll
            for (int d4 = 0; d4 < 32; d4 += 4) {
                const float4 kv = ld4(kp + d4);
                #pragma unroll
                for (int r = 0; r < 16; r++) {
                    const float4 qv = ld4(&q_s[(ib + 4 * r) * 32 + d4]);
                    acc[r] = fmaf(qv.x, kv.x, fmaf(qv.y, kv.y, fmaf(qv.z, kv.z, fmaf(qv.w, kv.w, acc[r]))));
                }
            }
            const float* mrow = attn_mask + (size_t)wrem * 4096;
            #pragma unroll
            for (int r = 0; r < 16; r++) {
                const int i  = ib + 4 * r;
                const int ri = rel_index[i * 64 + j];
                attn_s[i * 64 + j] = acc[r] + rpb[ri * 3 + hh] + mrow[i * 64 + j];
            }
        }
        __syncthreads();

        // ---- stage d: row softmax ----
        #pragma unroll
        for (int r = 0; r < 8; r++) {
            const int i = warp * 8 + r;
            float a0 = attn_s[i * 64 + lane];
            float a1 = attn_s[i * 64 + lane + 32];
            float m = fmaxf(a0, a1);
            #pragma unroll
            for (int o = 16; o; o >>= 1) m = fmaxf(m, __shfl_xor_sync(0xffffffffu, m, o));
            const float e0 = __expf(a0 - m), e1 = __expf(a1 - m);
            float s = e0 + e1;
            #pragma unroll
            for (int o = 16; o; o >>= 1) s += __shfl_xor_sync(0xffffffffu, s, o);
            const float inv = 1.0f / s;
            attn_s[i * 64 + lane]      = e0 * inv;
            attn_s[i * 64 + lane + 32] = e1 * inv;
        }
        __syncthreads();

        // ---- stage e: o = attn @ v (v transposed) ----
        {
            float acc[8];
            #pragma unroll
            for (int r = 0; r < 8; r++) acc[r] = 0.f;
            const float* vp = &v_s[d * 68];
            const float* ab = &attn_s[(ty * 8) * 64];
            #pragma unroll
            for (int j4 = 0; j4 < 64; j4 += 4) {
                const float4 vv = ld4(vp + j4);
                #pragma unroll
                for (int r = 0; r < 8; r++) {
                    const float4 av = ld4(ab + r * 64 + j4);
                    acc[r] = fmaf(av.x, vv.x, fmaf(av.y, vv.y, fmaf(av.z, vv.z, fmaf(av.w, vv.w, acc[r]))));
                }
            }
            #pragma unroll
            for (int r = 0; r < 8; r++)
                o_s[(ty * 8 + r) * 96 + hh * 32 + d] = acc[r];
        }
        __syncthreads();
    }

    // ---- proj + residual scatter ----
    for (int idx = tid; idx < 96 * 96; idx += 256)
        w_s[(idx / 96) * 100 + (idx % 96)] = proj_w[idx];
    __syncthreads();

    {
        float a0[8], a1[8], a2[8];
        #pragma unroll
        for (int r = 0; r < 8; r++) { a0[r] = 0.f; a1[r] = 0.f; a2[r] = 0.f; }
        const float* w0 = &w_s[d * 100];
        const float* w1 = &w_s[(32 + d) * 100];
        const float* w2 = &w_s[(64 + d) * 100];
        const float* ob = &o_s[(ty * 8) * 96];
        #pragma unroll
        for (int k4 = 0; k4 < 96; k4 += 4) {
            const float4 f0 = ld4(w0 + k4);
            const float4 f1 = ld4(w1 + k4);
            const float4 f2 = ld4(w2 + k4);
            #pragma unroll
            for (int r = 0; r < 8; r++) {
                const float4 ov = ld4(ob + r * 96 + k4);
                a0[r] = fmaf(ov.x, f0.x, fmaf(ov.y, f0.y, fmaf(ov.z, f0.z, fmaf(ov.w, f0.w, a0[r]))));
                a1[r] = fmaf(ov.x, f1.x, fmaf(ov.y, f1.y, fmaf(ov.z, f1.z, fmaf(ov.w, f1.w, a1[r]))));
                a2[r] = fmaf(ov.x, f2.x, fmaf(ov.y, f2.y, fmaf(ov.z, f2.z, fmaf(ov.w, f2.w, a2[r]))));
            }
        }
        const float pb0 = proj_b[d], pb1 = proj_b[32 + d], pb2 = proj_b[64 + d];
        #pragma unroll
        for (int r = 0; r < 8; r++) {
            const int t  = ty * 8 + r;
            const int iy = t >> 3, ix = t & 7;
            const int yy = (wy * 8 + iy + SSz) & 255;
            const int xx = (wx * 8 + ix + SSz) & 255;
            const size_t base = ((size_t)(b * 65536 + yy * 256 + xx)) * Cq;
            x2[base + d]      = x[base + d]      + a0[r] + pb0;
            x2[base + 32 + d] = x[base + 32 + d] + a1[r] + pb1;
            x2[base + 64 + d] = x[base + 64 + d] + a2[r] + pb2;
        }
    }
}

// ================= MLP kernel: 64 consecutive tokens per CTA =================
__global__ __launch_bounds__(256, 2)
void swin_mlp_kernel(const float* __restrict__ x2,
                     const float* __restrict__ g2, const float* __restrict__ b2,
                     const float* __restrict__ fc1_w, const float* __restrict__ fc1_b,
                     const float* __restrict__ fc2_w, const float* __restrict__ fc2_b,
                     float* __restrict__ out)
{
    extern __shared__ float smem[];
    float* x_s  = smem;            // [64][96]
    float* ln_s = x_s + 6144;      // [64][96]
    float* w_s  = ln_s + 6144;     // [96][100]
    float* h1_s = w_s + 9600;      // [64][96]

    const int tid  = threadIdx.x;
    const int lane = tid & 31;
    const int warp = tid >> 5;
    const size_t t0 = (size_t)blockIdx.x * 64;

    // ---- LayerNorm2 ----
    #pragma unroll
    for (int r = 0; r < 8; r++) {
        const int t = warp * 8 + r;
        const float* row = x2 + (t0 + t) * Cq;
        float v0 = row[lane], v1 = row[lane + 32], v2 = row[lane + 64];
        float s  = v0 + v1 + v2;
        float ss = v0 * v0 + v1 * v1 + v2 * v2;
        #pragma unroll
        for (int o = 16; o; o >>= 1) {
            s  += __shfl_xor_sync(0xffffffffu, s,  o);
            ss += __shfl_xor_sync(0xffffffffu, ss, o);
        }
        const float mu  = s * (1.0f / 96.0f);
        const float var = ss * (1.0f / 96.0f) - mu * mu;
        const float inv = rsqrtf(var + EPSq);
        x_s[t * 96 + lane]      = v0;
        x_s[t * 96 + lane + 32] = v1;
        x_s[t * 96 + lane + 64] = v2;
        ln_s[t * 96 + lane]      = (v0 - mu) * inv * g2[lane]      + b2[lane];
        ln_s[t * 96 + lane + 32] = (v1 - mu) * inv * g2[lane + 32] + b2[lane + 32];
        ln_s[t * 96 + lane + 64] = (v2 - mu) * inv * g2[lane + 64] + b2[lane + 64];
    }
    __syncthreads();

    const int d  = tid & 31;
    const int ty = tid >> 5;

    float o0[8], o1[8], o2[8];
    #pragma unroll
    for (int r = 0; r < 8; r++) { o0[r] = 0.f; o1[r] = 0.f; o2[r] = 0.f; }

    for (int jc = 0; jc < 4; jc++) {
        // stage fc1 chunk rows [jc*96, jc*96+96)
        for (int idx = tid; idx < 96 * 96; idx += 256) {
            const int j = idx / 96, c = idx - j * 96;
            w_s[j * 100 + c] = fc1_w[(jc * 96 + j) * 96 + c];
        }
        __syncthreads();

        // h1 chunk = gelu(ln @ W1^T + b1)   (8 rows x 3 cols per thread)
        {
            float a0[8], a1[8], a2[8];
            #pragma unroll
            for (int r = 0; r < 8; r++) { a0[r] = 0.f; a1[r] = 0.f; a2[r] = 0.f; }
            const float* w0 = &w_s[d * 100];
            const float* w1 = &w_s[(32 + d) * 100];
            const float* w2 = &w_s[(64 + d) * 100];
            const float* lb = &ln_s[(ty * 8) * 96];
            #pragma unroll
            for (int c4 = 0; c4 < 96; c4 += 4) {
                const float4 f0 = ld4(w0 + c4);
                const float4 f1 = ld4(w1 + c4);
                const float4 f2 = ld4(w2 + c4);
                #pragma unroll
                for (int r = 0; r < 8; r++) {
                    const float4 hv = ld4(lb + r * 96 + c4);
                    a0[r] = fmaf(hv.x, f0.x, fmaf(hv.y, f0.y, fmaf(hv.z, f0.z, fmaf(hv.w, f0.w, a0[r]))));
                    a1[r] = fmaf(hv.x, f1.x, fmaf(hv.y, f1.y, fmaf(hv.z, f1.z, fmaf(hv.w, f1.w, a1[r]))));
                    a2[r] = fmaf(hv.x, f2.x, fmaf(hv.y, f2.y, fmaf(hv.z, f2.z, fmaf(hv.w, f2.w, a2[r]))));
                }
            }
            const float bb0 = fc1_b[jc * 96 + d];
            const float bb1 = fc1_b[jc * 96 + 32 + d];
            const float bb2 = fc1_b[jc * 96 + 64 + d];
            #pragma unroll
            for (int r = 0; r < 8; r++) {
                const int t = ty * 8 + r;
                float v;
                v = a0[r] + bb0; h1_s[t * 96 + d]      = 0.5f * v * (1.0f + erff(v * 0.70710678118654752f));
                v = a1[r] + bb1; h1_s[t * 96 + 32 + d] = 0.5f * v * (1.0f + erff(v * 0.70710678118654752f));
                v = a2[r] + bb2; h1_s[t * 96 + 64 + d] = 0.5f * v * (1.0f + erff(v * 0.70710678118654752f));
            }
        }
        __syncthreads();

        // stage fc2 chunk: w_s[c][j] = fc2_w[c][jc*96 + j]
        for (int idx = tid; idx < 96 * 96; idx += 256) {
            const int c = idx / 96, j = idx - c * 96;
            w_s[c * 100 + j] = fc2_w[c * MLPH + jc * 96 + j];
        }
        __syncthreads();

        // out += h1chunk @ W2chunk^T
        {
            const float* w0 = &w_s[d * 100];
            const float* w1 = &w_s[(32 + d) * 100];
            const float* w2 = &w_s[(64 + d) * 100];
            const float* hb = &h1_s[(ty * 8) * 96];
            #pragma unroll
            for (int j4 = 0; j4 < 96; j4 += 4) {
                const float4 f0 = ld4(w0 + j4);
                const float4 f1 = ld4(w1 + j4);
                const float4 f2 = ld4(w2 + j4);
                #pragma unroll
                for (int r = 0; r < 8; r++) {
                    const float4 hv = ld4(hb + r * 96 + j4);
                    o0[r] = fmaf(hv.x, f0.x, fmaf(hv.y, f0.y, fmaf(hv.z, f0.z, fmaf(hv.w, f0.w, o0[r]))));
                    o1[r] = fmaf(hv.x, f1.x, fmaf(hv.y, f1.y, fmaf(hv.z, f1.z, fmaf(hv.w, f1.w, o1[r]))));
                    o2[r] = fmaf(hv.x, f2.x, fmaf(hv.y, f2.y, fmaf(hv.z, f2.z, fmaf(hv.w, f2.w, o2[r]))));
                }
            }
        }
        __syncthreads();
    }

    // ---- residual + store ----
    {
        const float bb0 = fc2_b[d], bb1 = fc2_b[32 + d], bb2 = fc2_b[64 + d];
        #pragma unroll
        for (int r = 0; r < 8; r++) {
            const int t = ty * 8 + r;
            out[(t0 + t) * Cq + d]      = x_s[t * 96 + d]      + o0[r] + bb0;
            out[(t0 + t) * Cq + 32 + d] = x_s[t * 96 + 32 + d] + o1[r] + bb1;
            out[(t0 + t) * Cq + 64 + d] = x_s[t * 96 + 64 + d] + o2[r] + bb2;
        }
    }
}

// ================= launch =================
extern "C" void kernel_launch(void* const* d_in, const int* in_sizes, int n_in,
                              void* d_out, int out_size)
{
    const float* x        = (const float*)d_in[0];
    const float* g1       = (const float*)d_in[1];
    const float* b1       = (const float*)d_in[2];
    const float* qkv_w    = (const float*)d_in[3];
    const float* qkv_b    = (const float*)d_in[4];
    const float* rpb      = (const float*)d_in[5];
    const float* proj_w   = (const float*)d_in[6];
    const float* proj_b   = (const float*)d_in[7];
    const float* g2       = (const float*)d_in[8];
    const float* b2       = (const float*)d_in[9];
    const float* fc1_w    = (const float*)d_in[10];
    const float* fc1_b    = (const float*)d_in[11];
    const float* fc2_w    = (const float*)d_in[12];
    const float* fc2_b    = (const float*)d_in[13];
    const float* attn_mask= (const float*)d_in[14];
    const int*   rel_index= (const int*)  d_in[15];
    float* out = (float*)d_out;

    const size_t a_smem = A_SMEM_FLOATS * sizeof(float);
    const size_t m_smem = M_SMEM_FLOATS * sizeof(float);
    cudaFuncSetAttribute(swin_attn_kernel, cudaFuncAttributeMaxDynamicSharedMemorySize, (int)a_smem);
    cudaFuncSetAttribute(swin_mlp_kernel,  cudaFuncAttributeMaxDynamicSharedMemorySize, (int)m_smem);

    float* x2;
    cudaGetSymbolAddress((void**)&x2, g_x2);

    swin_attn_kernel<<<Bq * NWq, 256, a_smem>>>(x, g1, b1, qkv_w, qkv_b, rpb,
                                                proj_w, proj_b, attn_mask, rel_index, x2);
    swin_mlp_kernel<<<TOKENS / 64, 256, m_smem>>>(x2, g2, b2, fc1_w, fc1_b,
                                                  fc2_w, fc2_b, out);
}

// round 4
// speedup vs baseline: 2.1886x; 1.7305x over previous
#include <cuda_runtime.h>
#include <cuda_bf16.h>
#include <math.h>
#include <stdint.h>

// ---------------- static config ----------------
#define Bq   4
#define Hq   256
#define Wq   256
#define Cq   96
#define WSz  8
#define SSz  4
#define NHq  3
#define Nq   64
#define NWq  1024
#define HDq  32
#define MLPH 384
#define TOKENS (Bq*Hq*Wq)
static __device__ float g_x2[(size_t)TOKENS * Cq];

#define SCALEq 0.17677669529663687f
#define EPSq   1e-5f

// ---------------- warp-mma helpers (sm_100 baseline: mma.sync + ldmatrix) ----
__device__ __forceinline__ uint32_t smem_u32(const void* p) {
    uint32_t a;
    asm("{ .reg .u64 t; cvta.to.shared.u64 t, %1; cvt.u32.u64 %0, t; }" : "=r"(a) : "l"(p));
    return a;
}
__device__ __forceinline__ void ldm4(uint32_t* r, uint32_t addr) {
    asm volatile("ldmatrix.sync.aligned.m8n8.x4.shared.b16 {%0,%1,%2,%3}, [%4];"
        : "=r"(r[0]), "=r"(r[1]), "=r"(r[2]), "=r"(r[3]) : "r"(addr));
}
__device__ __forceinline__ void mma_bf16(float* c, const uint32_t* a, const uint32_t* b) {
    asm volatile("mma.sync.aligned.m16n8k16.row.col.f32.bf16.bf16.f32 "
        "{%0,%1,%2,%3}, {%4,%5,%6,%7}, {%8,%9}, {%0,%1,%2,%3};"
        : "+f"(c[0]), "+f"(c[1]), "+f"(c[2]), "+f"(c[3])
        : "r"(a[0]), "r"(a[1]), "r"(a[2]), "r"(a[3]), "r"(b[0]), "r"(b[1]));
}
__device__ __forceinline__ float gelu_f(float v) {
    return 0.5f * v * (1.0f + erff(v * 0.70710678118654752f));
}
__device__ __forceinline__ uint32_t packbf(float a, float b) {
    const __nv_bfloat162 h = __floats2bfloat162_rn(a, b);
    return *(const uint32_t*)&h;
}

// ---------------- MLP smem layout (bf16 elements, strides in bf16) ----------
#define SA 104      // A [128][96]  rows stride 104 (208B, ldmatrix conflict-free)
#define SB1 104     // B1 chunk [128][96]
#define SB2 136     // B2 chunk [96][128]
#define SH 136      // H1 [128][128]
#define MS_A 0
#define MS_B (128*SA*2)                 // 26624
#define MS_H (MS_B + 128*SA*2)          // 53248
#define MS_TOTAL (MS_H + 128*SH*2)      // 88064

// ================= MLP kernel (mma.sync bf16): 128 tokens per CTA ==========
__global__ __launch_bounds__(256)
void swin_mlp_mma(const float* __restrict__ x2,
                  const float* __restrict__ g2, const float* __restrict__ b2,
                  const float* __restrict__ fc1_w, const float* __restrict__ fc1_b,
                  const float* __restrict__ fc2_w, const float* __restrict__ fc2_b,
                  float* __restrict__ out)
{
    extern __shared__ __align__(16) char smem[];
    const uint32_t sb = smem_u32(smem);
    const int tid = threadIdx.x, lane = tid & 31, w = tid >> 5;
    const size_t t0 = (size_t)blockIdx.x * 128;
    const int mrow0 = w * 16;

    // ---- LN2 -> A bf16 [128][96] ----
    #pragma unroll
    for (int r = 0; r < 16; r++) {
        const int t = w * 16 + r;
        const float* row = x2 + (t0 + t) * Cq;
        float v0 = row[lane], v1 = row[lane + 32], v2 = row[lane + 64];
        float s  = v0 + v1 + v2;
        float ss = v0 * v0 + v1 * v1 + v2 * v2;
        #pragma unroll
        for (int o = 16; o; o >>= 1) {
            s  += __shfl_xor_sync(0xffffffffu, s,  o);
            ss += __shfl_xor_sync(0xffffffffu, ss, o);
        }
        const float mu  = s * (1.0f / 96.0f);
        const float var = ss * (1.0f / 96.0f) - mu * mu;
        const float inv = rsqrtf(var + EPSq);
        __nv_bfloat16* arow = (__nv_bfloat16*)(smem + MS_A) + t * SA;
        arow[lane]      = __float2bfloat16((v0 - mu) * inv * g2[lane]      + b2[lane]);
        arow[lane + 32] = __float2bfloat16((v1 - mu) * inv * g2[lane + 32] + b2[lane + 32]);
        arow[lane + 64] = __float2bfloat16((v2 - mu) * inv * g2[lane + 64] + b2[lane + 64]);
    }
    __syncthreads();

    // ---- A fragments (persist: A reused across all 3 chunks) ----
    uint32_t afr[6][4];
    #pragma unroll
    for (int k = 0; k < 6; k++) {
        const uint32_t addr = sb + MS_A +
            (uint32_t)(((mrow0 + (lane & 15)) * SA + k * 16 + ((lane >> 4) << 3)) * 2);
        ldm4(afr[k], addr);
    }

    const int g = lane >> 2, tq = lane & 3;
    float ofr[6][2][4];
    #pragma unroll
    for (int i = 0; i < 6; i++)
        #pragma unroll
        for (int j = 0; j < 2; j++)
            #pragma unroll
            for (int q = 0; q < 4; q++) ofr[i][j][q] = 0.f;

    for (int chunk = 0; chunk < 3; chunk++) {
        // ---- stage B1 = fc1_w rows [chunk*128, +128) x K96 ----
        for (int idx = tid; idx < 128 * 48; idx += 256) {
            const int row = idx / 48, cp = (idx - row * 48) * 2;
            const float2 v = *(const float2*)(fc1_w + (size_t)(chunk * 128 + row) * 96 + cp);
            *(uint32_t*)(smem + MS_B + (row * SB1 + cp) * 2) = packbf(v.x, v.y);
        }
        __syncthreads();

        // ---- FC1: 16 n-tiles (2 at a time), K=96 ----
        #pragma unroll
        for (int nt2 = 0; nt2 < 8; nt2++) {
            const int n0 = nt2 * 16;
            float c0[4] = {0.f, 0.f, 0.f, 0.f}, c1[4] = {0.f, 0.f, 0.f, 0.f};
            #pragma unroll
            for (int k = 0; k < 6; k++) {
                uint32_t bfr[4];
                const uint32_t addr = sb + MS_B +
                    (uint32_t)(((n0 + (lane & 7) + ((lane & 16) ? 8 : 0)) * SB1
                               + k * 16 + ((lane & 8) ? 8 : 0)) * 2);
                ldm4(bfr, addr);
                mma_bf16(c0, afr[k], bfr);
                mma_bf16(c1, afr[k], bfr + 2);
            }
            // bias + gelu -> H1 bf16
            #pragma unroll
            for (int tile = 0; tile < 2; tile++) {
                float* c = tile ? c1 : c0;
                const int nn = n0 + tile * 8 + 2 * tq;
                const float bb0 = fc1_b[chunk * 128 + nn];
                const float bb1 = fc1_b[chunk * 128 + nn + 1];
                *(uint32_t*)(smem + MS_H + ((mrow0 + g) * SH + nn) * 2) =
                    packbf(gelu_f(c[0] + bb0), gelu_f(c[1] + bb1));
                *(uint32_t*)(smem + MS_H + ((mrow0 + g + 8) * SH + nn) * 2) =
                    packbf(gelu_f(c[2] + bb0), gelu_f(c[3] + bb1));
            }
        }
        __syncthreads();

        // ---- stage B2 = fc2_w[0..95][chunk*128 .. +128) ----
        for (int idx = tid; idx < 96 * 64; idx += 256) {
            const int row = idx >> 6, cp = (idx & 63) * 2;
            const float2 v = *(const float2*)(fc2_w + (size_t)row * MLPH + chunk * 128 + cp);
            *(uint32_t*)(smem + MS_B + (row * SB2 + cp) * 2) = packbf(v.x, v.y);
        }
        __syncthreads();

        // ---- FC2: accumulate 12 n-tiles, K=128 ----
        uint32_t hfr[8][4];
        #pragma unroll
        for (int k = 0; k < 8; k++) {
            const uint32_t addr = sb + MS_H +
                (uint32_t)(((mrow0 + (lane & 15)) * SH + k * 16 + ((lane >> 4) << 3)) * 2);
            ldm4(hfr[k], addr);
        }
        #pragma unroll
        for (int nt2 = 0; nt2 < 6; nt2++) {
            const int n0 = nt2 * 16;
            #pragma unroll
            for (int k = 0; k < 8; k++) {
                uint32_t bfr[4];
                const uint32_t addr = sb + MS_B +
                    (uint32_t)(((n0 + (lane & 7) + ((lane & 16) ? 8 : 0)) * SB2
                               + k * 16 + ((lane & 8) ? 8 : 0)) * 2);
                ldm4(bfr, addr);
                mma_bf16(ofr[nt2][0], hfr[k], bfr);
                mma_bf16(ofr[nt2][1], hfr[k], bfr + 2);
            }
        }
        __syncthreads();
    }

    // ---- epilogue: + fc2_b + residual -> out ----
    {
        const size_t rA = t0 + mrow0 + g;
        const size_t rB = rA + 8;
        const float* xA = x2 + rA * Cq;
        const float* xB = x2 + rB * Cq;
        float* oA = out + rA * Cq;
        float* oB = out + rB * Cq;
        #pragma unroll
        for (int nt2 = 0; nt2 < 6; nt2++) {
            #pragma unroll
            for (int tile = 0; tile < 2; tile++) {
                const int n = nt2 * 16 + tile * 8 + 2 * tq;
                const float* c = ofr[nt2][tile];
                const float b0 = fc2_b[n], b1 = fc2_b[n + 1];
                *(float2*)(oA + n) = make_float2(xA[n] + c[0] + b0, xA[n + 1] + c[1] + b1);
                *(float2*)(oB + n) = make_float2(xB[n] + c[2] + b0, xB[n + 1] + c[3] + b1);
            }
        }
    }
}

__device__ __forceinline__ float4 ld4(const float* p) { return *(const float4*)p; }

// ---------------- attention kernel (round-2, unchanged) ----------------
#define A_SMEM_FLOATS (6144 + 9600 + 2048 + 2304 + 2176 + 6144)

__global__ __launch_bounds__(256, 2)
void swin_attn_kernel(const float* __restrict__ x,
                      const float* __restrict__ g1, const float* __restrict__ b1,
                      const float* __restrict__ qkv_w, const float* __restrict__ qkv_b,
                      const float* __restrict__ rpb,
                      const float* __restrict__ proj_w, const float* __restrict__ proj_b,
                      const float* __restrict__ attn_mask,
                      const int*   __restrict__ rel_index,
                      float* __restrict__ x2)
{
    extern __shared__ float fsmem[];
    float* h_s    = fsmem;
    float* w_s    = h_s + 6144;
    float* attn_s = w_s;
    float* q_s    = w_s + 9600;
    float* k_s    = q_s + 2048;
    float* v_s    = k_s + 2304;
    float* o_s    = v_s + 2176;

    const int tid  = threadIdx.x;
    const int lane = tid & 31;
    const int warp = tid >> 5;
    const int w    = blockIdx.x;
    const int b    = w >> 10;
    const int wrem = w & 1023;
    const int wy   = wrem >> 5;
    const int wx   = wrem & 31;

    #pragma unroll
    for (int r = 0; r < 8; r++) {
        const int t  = warp * 8 + r;
        const int iy = t >> 3, ix = t & 7;
        const int yy = (wy * 8 + iy + SSz) & 255;
        const int xx = (wx * 8 + ix + SSz) & 255;
        const int tok = b * 65536 + yy * 256 + xx;
        const float* row = x + (size_t)tok * Cq;
        float v0 = row[lane], v1 = row[lane + 32], v2 = row[lane + 64];
        float s  = v0 + v1 + v2;
        float ss = v0 * v0 + v1 * v1 + v2 * v2;
        #pragma unroll
        for (int o = 16; o; o >>= 1) {
            s  += __shfl_xor_sync(0xffffffffu, s,  o);
            ss += __shfl_xor_sync(0xffffffffu, ss, o);
        }
        const float mu  = s * (1.0f / 96.0f);
        const float var = ss * (1.0f / 96.0f) - mu * mu;
        const float inv = rsqrtf(var + EPSq);
        h_s[t * 96 + lane]      = (v0 - mu) * inv * g1[lane]      + b1[lane];
        h_s[t * 96 + lane + 32] = (v1 - mu) * inv * g1[lane + 32] + b1[lane + 32];
        h_s[t * 96 + lane + 64] = (v2 - mu) * inv * g1[lane + 64] + b1[lane + 64];
    }
    __syncthreads();

    const int d  = tid & 31;
    const int ty = tid >> 5;

    for (int hh = 0; hh < NHq; hh++) {
        for (int idx = tid; idx < 96 * 96; idx += 256) {
            const int rr = idx / 96, c = idx - rr * 96;
            const int grow = (rr >> 5) * 96 + hh * 32 + (rr & 31);
            w_s[rr * 100 + c] = qkv_w[grow * 96 + c];
        }
        __syncthreads();

        {
            float aq[8], ak[8], av[8];
            #pragma unroll
            for (int r = 0; r < 8; r++) { aq[r] = 0.f; ak[r] = 0.f; av[r] = 0.f; }
            const float* wq = &w_s[d * 100];
            const float* wk = &w_s[(32 + d) * 100];
            const float* wv = &w_s[(64 + d) * 100];
            const float* hb = &h_s[(ty * 8) * 96];
            #pragma unroll
            for (int c4 = 0; c4 < 96; c4 += 4) {
                const float4 fq = ld4(wq + c4);
                const float4 fk = ld4(wk + c4);
                const float4 fv = ld4(wv + c4);
                #pragma unroll
                for (int r = 0; r < 8; r++) {
                    const float4 hv = ld4(hb + r * 96 + c4);
                    aq[r] = fmaf(hv.x, fq.x, fmaf(hv.y, fq.y, fmaf(hv.z, fq.z, fmaf(hv.w, fq.w, aq[r]))));
                    ak[r] = fmaf(hv.x, fk.x, fmaf(hv.y, fk.y, fmaf(hv.z, fk.z, fmaf(hv.w, fk.w, ak[r]))));
                    av[r] = fmaf(hv.x, fv.x, fmaf(hv.y, fv.y, fmaf(hv.z, fv.z, fmaf(hv.w, fv.w, av[r]))));
                }
            }
            const float bq = qkv_b[hh * 32 + d];
            const float bk = qkv_b[96 + hh * 32 + d];
            const float bv = qkv_b[192 + hh * 32 + d];
            #pragma unroll
            for (int r = 0; r < 8; r++) {
                const int t = ty * 8 + r;
                q_s[t * 32 + d] = (aq[r] + bq) * SCALEq;
                k_s[t * 36 + d] = ak[r] + bk;
                v_s[d * 68 + t] = av[r] + bv;
            }
        }
        __syncthreads();

        {
            const int j  = tid & 63;
            const int ib = tid >> 6;
            float acc[16];
            #pragma unroll
            for (int r = 0; r < 16; r++) acc[r] = 0.f;
            const float* kp = &k_s[j * 36];
            #pragma unroll
            for (int d4 = 0; d4 < 32; d4 += 4) {
                const float4 kv = ld4(kp + d4);
                #pragma unroll
                for (int r = 0; r < 16; r++) {
                    const float4 qv = ld4(&q_s[(ib + 4 * r) * 32 + d4]);
                    acc[r] = fmaf(qv.x, kv.x, fmaf(qv.y, kv.y, fmaf(qv.z, kv.z, fmaf(qv.w, kv.w, acc[r]))));
                }
            }
            const float* mrow = attn_mask + (size_t)wrem * 4096;
            #pragma unroll
            for (int r = 0; r < 16; r++) {
                const int i  = ib + 4 * r;
                const int ri = rel_index[i * 64 + j];
                attn_s[i * 64 + j] = acc[r] + rpb[ri * 3 + hh] + mrow[i * 64 + j];
            }
        }
        __syncthreads();

        #pragma unroll
        for (int r = 0; r < 8; r++) {
            const int i = warp * 8 + r;
            float a0 = attn_s[i * 64 + lane];
            float a1 = attn_s[i * 64 + lane + 32];
            float m = fmaxf(a0, a1);
            #pragma unroll
            for (int o = 16; o; o >>= 1) m = fmaxf(m, __shfl_xor_sync(0xffffffffu, m, o));
            const float e0 = __expf(a0 - m), e1 = __expf(a1 - m);
            float s = e0 + e1;
            #pragma unroll
            for (int o = 16; o; o >>= 1) s += __shfl_xor_sync(0xffffffffu, s, o);
            const float inv = 1.0f / s;
            attn_s[i * 64 + lane]      = e0 * inv;
            attn_s[i * 64 + lane + 32] = e1 * inv;
        }
        __syncthreads();

        {
            float acc[8];
            #pragma unroll
            for (int r = 0; r < 8; r++) acc[r] = 0.f;
            const float* vp = &v_s[d * 68];
            const float* ab = &attn_s[(ty * 8) * 64];
            #pragma unroll
            for (int j4 = 0; j4 < 64; j4 += 4) {
                const float4 vv = ld4(vp + j4);
                #pragma unroll
                for (int r = 0; r < 8; r++) {
                    const float4 av = ld4(ab + r * 64 + j4);
                    acc[r] = fmaf(av.x, vv.x, fmaf(av.y, vv.y, fmaf(av.z, vv.z, fmaf(av.w, vv.w, acc[r]))));
                }
            }
            #pragma unroll
            for (int r = 0; r < 8; r++)
                o_s[(ty * 8 + r) * 96 + hh * 32 + d] = acc[r];
        }
        __syncthreads();
    }

    for (int idx = tid; idx < 96 * 96; idx += 256)
        w_s[(idx / 96) * 100 + (idx % 96)] = proj_w[idx];
    __syncthreads();

    {
        float a0[8], a1[8], a2[8];
        #pragma unroll
        for (int r = 0; r < 8; r++) { a0[r] = 0.f; a1[r] = 0.f; a2[r] = 0.f; }
        const float* w0 = &w_s[d * 100];
        const float* w1 = &w_s[(32 + d) * 100];
        const float* w2 = &w_s[(64 + d) * 100];
        const float* ob = &o_s[(ty * 8) * 96];
        #pragma unroll
        for (int k4 = 0; k4 < 96; k4 += 4) {
            const float4 f0 = ld4(w0 + k4);
            const float4 f1 = ld4(w1 + k4);
            const float4 f2 = ld4(w2 + k4);
            #pragma unroll
            for (int r = 0; r < 8; r++) {
                const float4 ov = ld4(ob + r * 96 + k4);
                a0[r] = fmaf(ov.x, f0.x, fmaf(ov.y, f0.y, fmaf(ov.z, f0.z, fmaf(ov.w, f0.w, a0[r]))));
                a1[r] = fmaf(ov.x, f1.x, fmaf(ov.y, f1.y, fmaf(ov.z, f1.z, fmaf(ov.w, f1.w, a1[r]))));
                a2[r] = fmaf(ov.x, f2.x, fmaf(ov.y, f2.y, fmaf(ov.z, f2.z, fmaf(ov.w, f2.w, a2[r]))));
            }
        }
        const float pb0 = proj_b[d], pb1 = proj_b[32 + d], pb2 = proj_b[64 + d];
        #pragma unroll
        for (int r = 0; r < 8; r++) {
            const int t  = ty * 8 + r;
            const int iy = t >> 3, ix = t & 7;
            const int yy = (wy * 8 + iy + SSz) & 255;
            const int xx = (wx * 8 + ix + SSz) & 255;
            const size_t base = ((size_t)(b * 65536 + yy * 256 + xx)) * Cq;
            x2[base + d]      = x[base + d]      + a0[r] + pb0;
            x2[base + 32 + d] = x[base + 32 + d] + a1[r] + pb1;
            x2[base + 64 + d] = x[base + 64 + d] + a2[r] + pb2;
        }
    }
}

// ================= launch =================
extern "C" void kernel_launch(void* const* d_in, const int* in_sizes, int n_in,
                              void* d_out, int out_size)
{
    const float* x        = (const float*)d_in[0];
    const float* g1       = (const float*)d_in[1];
    const float* b1       = (const float*)d_in[2];
    const float* qkv_w    = (const float*)d_in[3];
    const float* qkv_b    = (const float*)d_in[4];
    const float* rpb      = (const float*)d_in[5];
    const float* proj_w   = (const float*)d_in[6];
    const float* proj_b   = (const float*)d_in[7];
    const float* g2       = (const float*)d_in[8];
    const float* b2       = (const float*)d_in[9];
    const float* fc1_w    = (const float*)d_in[10];
    const float* fc1_b    = (const float*)d_in[11];
    const float* fc2_w    = (const float*)d_in[12];
    const float* fc2_b    = (const float*)d_in[13];
    const float* attn_mask= (const float*)d_in[14];
    const int*   rel_index= (const int*)  d_in[15];
    float* out = (float*)d_out;

    const size_t a_smem = A_SMEM_FLOATS * sizeof(float);
    cudaFuncSetAttribute(swin_attn_kernel, cudaFuncAttributeMaxDynamicSharedMemorySize, (int)a_smem);
    cudaFuncSetAttribute(swin_mlp_mma, cudaFuncAttributeMaxDynamicSharedMemorySize, MS_TOTAL);

    float* x2;
    cudaGetSymbolAddress((void**)&x2, g_x2);

    swin_attn_kernel<<<Bq * NWq, 256, a_smem>>>(x, g1, b1, qkv_w, qkv_b, rpb,
                                                proj_w, proj_b, attn_mask, rel_index, x2);
    swin_mlp_mma<<<TOKENS / 128, 256, MS_TOTAL>>>(x2, g2, b2, fc1_w, fc1_b,
                                                  fc2_w, fc2_b, out);
}

// round 6
// speedup vs baseline: 5.1308x; 2.3443x over previous
#include <cuda_runtime.h>
#include <cuda_bf16.h>
#include <math.h>
#include <stdint.h>

// ---------------- static config ----------------
#define Bq   4
#define Hq   256
#define Wq   256
#define Cq   96
#define WSz  8
#define SSz  4
#define NHq  3
#define Nq   64
#define NWq  1024
#define HDq  32
#define MLPH 384
#define TOKENS (Bq*Hq*Wq)
static __device__ float g_x2[(size_t)TOKENS * Cq];
static __device__ __nv_bfloat16 g_bias[3 * 64 * 64];   // gathered rel-pos bias, bf16

#define SCALEq 0.17677669529663687f
#define EPSq   1e-5f

// ---------------- warp-mma helpers ----------------
__device__ __forceinline__ uint32_t smem_u32(const void* p) {
    uint32_t a;
    asm("{ .reg .u64 t; cvta.to.shared.u64 t, %1; cvt.u32.u64 %0, t; }" : "=r"(a) : "l"(p));
    return a;
}
__device__ __forceinline__ void ldm4(uint32_t* r, uint32_t addr) {
    asm volatile("ldmatrix.sync.aligned.m8n8.x4.shared.b16 {%0,%1,%2,%3}, [%4];"
        : "=r"(r[0]), "=r"(r[1]), "=r"(r[2]), "=r"(r[3]) : "r"(addr));
}
__device__ __forceinline__ void mma_bf16(float* c, const uint32_t* a, const uint32_t* b) {
    asm volatile("mma.sync.aligned.m16n8k16.row.col.f32.bf16.bf16.f32 "
        "{%0,%1,%2,%3}, {%4,%5,%6,%7}, {%8,%9}, {%0,%1,%2,%3};"
        : "+f"(c[0]), "+f"(c[1]), "+f"(c[2]), "+f"(c[3])
        : "r"(a[0]), "r"(a[1]), "r"(a[2]), "r"(a[3]), "r"(b[0]), "r"(b[1]));
}
__device__ __forceinline__ float gelu_f(float v) {
    return 0.5f * v * (1.0f + erff(v * 0.70710678118654752f));
}
__device__ __forceinline__ uint32_t packbf(float a, float b) {
    const __nv_bfloat162 h = __floats2bfloat162_rn(a, b);
    return *(const uint32_t*)&h;
}
__device__ __forceinline__ float2 unpackbf(uint32_t u) {
    const __nv_bfloat162 h = *(const __nv_bfloat162*)&u;
    return make_float2(__bfloat162float(h.x), __bfloat162float(h.y));
}

// ================= prep: gathered bias table (bf16) =================
__global__ void prep_bias_kernel(const float* __restrict__ rpb, const int* __restrict__ rel_index)
{
    const int idx = blockIdx.x * 256 + threadIdx.x;   // 48*256 = 12288
    if (idx < 3 * 4096) {
        const int hh = idx >> 12, ij = idx & 4095;
        g_bias[hh * 4096 + ij] = __float2bfloat16(rpb[rel_index[ij] * 3 + hh]);
    }
}

// ---------------- attention smem layout (bytes) ----------------
#define SAT 104     // a_s / k_s row stride (bf16)
#define SVT 136     // vt_s row stride (bf16)
#define AS_A  0                      // a_s [128][104] bf16 -> later o_s
#define AS_K  26624                  // k_s [128][104] bf16
#define AS_VT 53248                  // vt_s [96][136] bf16 (v transposed, col = wl*64+t)
#define AS_W  79360                  // w_s [96][104] bf16 weight chunk
#define AS_TOTAL 99328

// ================= Attention (mma.sync bf16): 2 windows / CTA =================
__global__ __launch_bounds__(256, 2)
void swin_attn_mma(const float* __restrict__ x,
                   const float* __restrict__ g1, const float* __restrict__ b1,
                   const float* __restrict__ qkv_w, const float* __restrict__ qkv_b,
                   const float* __restrict__ proj_w, const float* __restrict__ proj_b,
                   const float* __restrict__ attn_mask,
                   float* __restrict__ x2)
{
    extern __shared__ __align__(16) char smem[];
    const uint32_t sb = smem_u32(smem);
    const int tid = threadIdx.x, lane = tid & 31, warp = tid >> 5;
    const int blk = blockIdx.x;

    const int wglob = blk * 2 + (warp >> 2);
    const int b     = wglob >> 10;
    const int wrem  = wglob & 1023;
    const int wy    = wrem >> 5, wx = wrem & 31;
    const int wl    = warp >> 2;          // window slot in CTA
    const int mrow0 = warp * 16;          // CTA token row base for this warp

    // ---- LN1 + gather -> a_s bf16 [128][104] ----
    #pragma unroll
    for (int r = 0; r < 16; r++) {
        const int t = mrow0 + r;
        const int i = t & 63;
        const int iy = i >> 3, ix = i & 7;
        const int yy = (wy * 8 + iy + SSz) & 255;
        const int xx = (wx * 8 + ix + SSz) & 255;
        const float* row = x + (size_t)(b * 65536 + yy * 256 + xx) * Cq;
        float v0 = row[lane], v1 = row[lane + 32], v2 = row[lane + 64];
        float s  = v0 + v1 + v2;
        float ss = v0 * v0 + v1 * v1 + v2 * v2;
        #pragma unroll
        for (int o = 16; o; o >>= 1) {
            s  += __shfl_xor_sync(0xffffffffu, s,  o);
            ss += __shfl_xor_sync(0xffffffffu, ss, o);
        }
        const float mu  = s * (1.0f / 96.0f);
        const float var = ss * (1.0f / 96.0f) - mu * mu;
        const float inv = rsqrtf(var + EPSq);
        __nv_bfloat16* arow = (__nv_bfloat16*)(smem + AS_A) + t * SAT;
        arow[lane]      = __float2bfloat16((v0 - mu) * inv * g1[lane]      + b1[lane]);
        arow[lane + 32] = __float2bfloat16((v1 - mu) * inv * g1[lane + 32] + b1[lane + 32]);
        arow[lane + 64] = __float2bfloat16((v2 - mu) * inv * g1[lane + 64] + b1[lane + 64]);
    }
    __syncthreads();

    // ---- A fragments (reused across all 3 qkv chunks) ----
    uint32_t afr[6][4];
    #pragma unroll
    for (int k = 0; k < 6; k++)
        ldm4(afr[k], sb + AS_A + (uint32_t)(((mrow0 + (lane & 15)) * SAT + k * 16 + ((lane >> 4) << 3)) * 2));

    const int g = lane >> 2, tq = lane & 3;

    // ---- QKV: 3 chunks (Q, K, V) ----
    uint32_t qafr[6][4];
    #pragma unroll
    for (int chunk = 0; chunk < 3; chunk++) {
        for (int idx = tid; idx < 96 * 48; idx += 256) {
            const int row = idx / 48, cp = (idx - row * 48) * 2;
            const float2 v = *(const float2*)(qkv_w + (size_t)(chunk * 96 + row) * 96 + cp);
            *(uint32_t*)(smem + AS_W + (row * SAT + cp) * 2) = packbf(v.x, v.y);
        }
        __syncthreads();

        #pragma unroll
        for (int nt2 = 0; nt2 < 6; nt2++) {
            float c0[4] = {0.f,0.f,0.f,0.f}, c1[4] = {0.f,0.f,0.f,0.f};
            #pragma unroll
            for (int kt = 0; kt < 6; kt++) {
                uint32_t bfr[4];
                ldm4(bfr, sb + AS_W + (uint32_t)(((nt2 * 16 + (lane & 7) + ((lane & 16) ? 8 : 0)) * SAT
                                                 + kt * 16 + ((lane & 8) ? 8 : 0)) * 2));
                mma_bf16(c0, afr[kt], bfr);
                mma_bf16(c1, afr[kt], bfr + 2);
            }
            const int n = nt2 * 16 + 2 * tq;
            if (chunk == 0) {
                const float b0 = qkv_b[n],     b1v = qkv_b[n + 1];
                const float b8 = qkv_b[n + 8], b9  = qkv_b[n + 9];
                qafr[nt2][0] = packbf((c0[0] + b0) * SCALEq, (c0[1] + b1v) * SCALEq);
                qafr[nt2][1] = packbf((c0[2] + b0) * SCALEq, (c0[3] + b1v) * SCALEq);
                qafr[nt2][2] = packbf((c1[0] + b8) * SCALEq, (c1[1] + b9) * SCALEq);
                qafr[nt2][3] = packbf((c1[2] + b8) * SCALEq, (c1[3] + b9) * SCALEq);
            } else if (chunk == 1) {
                const float b0 = qkv_b[96 + n],     b1v = qkv_b[96 + n + 1];
                const float b8 = qkv_b[96 + n + 8], b9  = qkv_b[96 + n + 9];
                *(uint32_t*)(smem + AS_K + (((mrow0 + g)     * SAT) + n)     * 2) = packbf(c0[0] + b0, c0[1] + b1v);
                *(uint32_t*)(smem + AS_K + (((mrow0 + g + 8) * SAT) + n)     * 2) = packbf(c0[2] + b0, c0[3] + b1v);
                *(uint32_t*)(smem + AS_K + (((mrow0 + g)     * SAT) + n + 8) * 2) = packbf(c1[0] + b8, c1[1] + b9);
                *(uint32_t*)(smem + AS_K + (((mrow0 + g + 8) * SAT) + n + 8) * 2) = packbf(c1[2] + b8, c1[3] + b9);
            } else {
                const float b0 = qkv_b[192 + n],     b1v = qkv_b[192 + n + 1];
                const float b8 = qkv_b[192 + n + 8], b9  = qkv_b[192 + n + 9];
                const int il = (warp & 3) * 16 + g;          // token within window
                const int cc = wl * 64 + il;
                __nv_bfloat16* vt = (__nv_bfloat16*)(smem + AS_VT);
                vt[(n)     * SVT + cc]     = __float2bfloat16(c0[0] + b0);
                vt[(n + 1) * SVT + cc]     = __float2bfloat16(c0[1] + b1v);
                vt[(n)     * SVT + cc + 8] = __float2bfloat16(c0[2] + b0);
                vt[(n + 1) * SVT + cc + 8] = __float2bfloat16(c0[3] + b1v);
                vt[(n + 8) * SVT + cc]     = __float2bfloat16(c1[0] + b8);
                vt[(n + 9) * SVT + cc]     = __float2bfloat16(c1[1] + b9);
                vt[(n + 8) * SVT + cc + 8] = __float2bfloat16(c1[2] + b8);
                vt[(n + 9) * SVT + cc + 8] = __float2bfloat16(c1[3] + b9);
            }
        }
        __syncthreads();
    }

    // ---- preload mask (16 packed bf16x2, reused over heads) ----
    const int i0 = (warp & 3) * 16;
    uint32_t mreg[16];
    {
        const float* mbase = attn_mask + (size_t)wrem * 4096;
        #pragma unroll
        for (int nt2 = 0; nt2 < 4; nt2++)
            #pragma unroll
            for (int t2 = 0; t2 < 2; t2++) {
                const int col = nt2 * 16 + t2 * 8 + 2 * tq;
                const int id = (nt2 * 2 + t2) * 2;
                mreg[id]     = packbf(mbase[(i0 + g) * 64 + col],     mbase[(i0 + g) * 64 + col + 1]);
                mreg[id + 1] = packbf(mbase[(i0 + g + 8) * 64 + col], mbase[(i0 + g + 8) * 64 + col + 1]);
            }
    }

    // ---- per-head: S = Q K^T, softmax, O = P V ----
    for (int hh = 0; hh < NHq; hh++) {
        float sc[4][8];
        #pragma unroll
        for (int nt2 = 0; nt2 < 4; nt2++) {
            #pragma unroll
            for (int q = 0; q < 8; q++) sc[nt2][q] = 0.f;
            #pragma unroll
            for (int kt2 = 0; kt2 < 2; kt2++) {
                uint32_t bfr[4];
                ldm4(bfr, sb + AS_K + (uint32_t)(((wl * 64 + nt2 * 16 + (lane & 7) + ((lane & 16) ? 8 : 0)) * SAT
                                                 + hh * 32 + kt2 * 16 + ((lane & 8) ? 8 : 0)) * 2));
                mma_bf16(sc[nt2],     qafr[2 * hh + kt2], bfr);
                mma_bf16(sc[nt2] + 4, qafr[2 * hh + kt2], bfr + 2);
            }
        }
        // bias + mask
        const __nv_bfloat16* bias_h = g_bias + hh * 4096;
        #pragma unroll
        for (int nt2 = 0; nt2 < 4; nt2++)
            #pragma unroll
            for (int t2 = 0; t2 < 2; t2++) {
                const int col = nt2 * 16 + t2 * 8 + 2 * tq;
                #pragma unroll
                for (int rs = 0; rs < 2; rs++) {
                    float* cp = &sc[nt2][t2 * 4 + rs * 2];
                    const uint32_t bu = *(const uint32_t*)(bias_h + (i0 + g + rs * 8) * 64 + col);
                    const float2 bv = unpackbf(bu);
                    const float2 mv = unpackbf(mreg[(nt2 * 2 + t2) * 2 + rs]);
                    cp[0] += bv.x + mv.x;
                    cp[1] += bv.y + mv.y;
                }
            }
        // softmax (rows g and g+8)
        float mx0 = -1e30f, mx1 = -1e30f;
        #pragma unroll
        for (int nt2 = 0; nt2 < 4; nt2++)
            #pragma unroll
            for (int t2 = 0; t2 < 2; t2++) {
                mx0 = fmaxf(mx0, fmaxf(sc[nt2][t2 * 4],     sc[nt2][t2 * 4 + 1]));
                mx1 = fmaxf(mx1, fmaxf(sc[nt2][t2 * 4 + 2], sc[nt2][t2 * 4 + 3]));
            }
        mx0 = fmaxf(mx0, __shfl_xor_sync(0xffffffffu, mx0, 1));
        mx0 = fmaxf(mx0, __shfl_xor_sync(0xffffffffu, mx0, 2));
        mx1 = fmaxf(mx1, __shfl_xor_sync(0xffffffffu, mx1, 1));
        mx1 = fmaxf(mx1, __shfl_xor_sync(0xffffffffu, mx1, 2));
        float s0 = 0.f, s1 = 0.f;
        #pragma unroll
        for (int nt2 = 0; nt2 < 4; nt2++)
            #pragma unroll
            for (int t2 = 0; t2 < 2; t2++) {
                float* cp = &sc[nt2][t2 * 4];
                cp[0] = __expf(cp[0] - mx0); cp[1] = __expf(cp[1] - mx0);
                cp[2] = __expf(cp[2] - mx1); cp[3] = __expf(cp[3] - mx1);
                s0 += cp[0] + cp[1];
                s1 += cp[2] + cp[3];
            }
        s0 += __shfl_xor_sync(0xffffffffu, s0, 1);
        s0 += __shfl_xor_sync(0xffffffffu, s0, 2);
        s1 += __shfl_xor_sync(0xffffffffu, s1, 1);
        s1 += __shfl_xor_sync(0xffffffffu, s1, 2);
        const float inv0 = 1.0f / s0, inv1 = 1.0f / s1;
        // P as A-fragments (register reuse)
        uint32_t pa[4][4];
        #pragma unroll
        for (int kt = 0; kt < 4; kt++) {
            pa[kt][0] = packbf(sc[kt][0] * inv0, sc[kt][1] * inv0);
            pa[kt][1] = packbf(sc[kt][2] * inv1, sc[kt][3] * inv1);
            pa[kt][2] = packbf(sc[kt][4] * inv0, sc[kt][5] * inv0);
            pa[kt][3] = packbf(sc[kt][6] * inv1, sc[kt][7] * inv1);
        }
        // O = P V  -> o_s (reuses a_s)
        #pragma unroll
        for (int nb = 0; nb < 2; nb++) {
            float oc0[4] = {0.f,0.f,0.f,0.f}, oc1[4] = {0.f,0.f,0.f,0.f};
            #pragma unroll
            for (int kt = 0; kt < 4; kt++) {
                uint32_t bfr[4];
                ldm4(bfr, sb + AS_VT + (uint32_t)(((hh * 32 + nb * 16 + (lane & 7) + ((lane & 16) ? 8 : 0)) * SVT
                                                  + wl * 64 + kt * 16 + ((lane & 8) ? 8 : 0)) * 2));
                mma_bf16(oc0, pa[kt], bfr);
                mma_bf16(oc1, pa[kt], bfr + 2);
            }
            const int col = hh * 32 + nb * 16 + 2 * tq;
            *(uint32_t*)(smem + AS_A + (((mrow0 + g)     * SAT) + col)     * 2) = packbf(oc0[0], oc0[1]);
            *(uint32_t*)(smem + AS_A + (((mrow0 + g + 8) * SAT) + col)     * 2) = packbf(oc0[2], oc0[3]);
            *(uint32_t*)(smem + AS_A + (((mrow0 + g)     * SAT) + col + 8) * 2) = packbf(oc1[0], oc1[1]);
            *(uint32_t*)(smem + AS_A + (((mrow0 + g + 8) * SAT) + col + 8) * 2) = packbf(oc1[2], oc1[3]);
        }
    }
    __syncthreads();

    // ---- proj: stage proj_w [96][96] ----
    for (int idx = tid; idx < 96 * 48; idx += 256) {
        const int row = idx / 48, cp = (idx - row * 48) * 2;
        const float2 v = *(const float2*)(proj_w + (size_t)row * 96 + cp);
        *(uint32_t*)(smem + AS_W + (row * SAT + cp) * 2) = packbf(v.x, v.y);
    }
    __syncthreads();

    uint32_t ofr[6][4];
    #pragma unroll
    for (int k = 0; k < 6; k++)
        ldm4(ofr[k], sb + AS_A + (uint32_t)(((mrow0 + (lane & 15)) * SAT + k * 16 + ((lane >> 4) << 3)) * 2));

    // residual base addresses for the two rows this thread owns
    size_t baseA, baseB;
    {
        const int tA = mrow0 + g, tB = tA + 8;
        const int iA = tA & 63, iB = tB & 63;
        const int yyA = (wy * 8 + (iA >> 3) + SSz) & 255, xxA = (wx * 8 + (iA & 7) + SSz) & 255;
        const int yyB = (wy * 8 + (iB >> 3) + SSz) & 255, xxB = (wx * 8 + (iB & 7) + SSz) & 255;
        baseA = ((size_t)(b * 65536 + yyA * 256 + xxA)) * Cq;
        baseB = ((size_t)(b * 65536 + yyB * 256 + xxB)) * Cq;
    }

    #pragma unroll
    for (int nt2 = 0; nt2 < 6; nt2++) {
        float c0[4] = {0.f,0.f,0.f,0.f}, c1[4] = {0.f,0.f,0.f,0.f};
        #pragma unroll
        for (int kt = 0; kt < 6; kt++) {
            uint32_t bfr[4];
            ldm4(bfr, sb + AS_W + (uint32_t)(((nt2 * 16 + (lane & 7) + ((lane & 16) ? 8 : 0)) * SAT
                                             + kt * 16 + ((lane & 8) ? 8 : 0)) * 2));
            mma_bf16(c0, ofr[kt], bfr);
            mma_bf16(c1, ofr[kt], bfr + 2);
        }
        const int n = nt2 * 16 + 2 * tq;
        {
            const float b0 = proj_b[n], b1v = proj_b[n + 1];
            const float2 xA = *(const float2*)(x + baseA + n);
            const float2 xB = *(const float2*)(x + baseB + n);
            *(float2*)(x2 + baseA + n) = make_float2(xA.x + c0[0] + b0, xA.y + c0[1] + b1v);
            *(float2*)(x2 + baseB + n) = make_float2(xB.x + c0[2] + b0, xB.y + c0[3] + b1v);
        }
        {
            const float b0 = proj_b[n + 8], b1v = proj_b[n + 9];
            const float2 xA = *(const float2*)(x + baseA + n + 8);
            const float2 xB = *(const float2*)(x + baseB + n + 8);
            *(float2*)(x2 + baseA + n + 8) = make_float2(xA.x + c1[0] + b0, xA.y + c1[1] + b1v);
            *(float2*)(x2 + baseB + n + 8) = make_float2(xB.x + c1[2] + b0, xB.y + c1[3] + b1v);
        }
    }
}

// ---------------- MLP smem layout (bf16 elements, strides in bf16) ----------
#define SA 104
#define SB1 104
#define SB2 136
#define SH 136
#define MS_A 0
#define MS_B (128*SA*2)
#define MS_H (MS_B + 128*SA*2)
#define MS_TOTAL (MS_H + 128*SH*2)

// ================= MLP kernel (mma.sync bf16): 128 tokens per CTA ==========
__global__ __launch_bounds__(256)
void swin_mlp_mma(const float* __restrict__ x2,
                  const float* __restrict__ g2, const float* __restrict__ b2,
                  const float* __restrict__ fc1_w, const float* __restrict__ fc1_b,
                  const float* __restrict__ fc2_w, const float* __restrict__ fc2_b,
                  float* __restrict__ out)
{
    extern __shared__ __align__(16) char smem[];
    const uint32_t sb = smem_u32(smem);
    const int tid = threadIdx.x, lane = tid & 31, w = tid >> 5;
    const size_t t0 = (size_t)blockIdx.x * 128;
    const int mrow0 = w * 16;

    #pragma unroll
    for (int r = 0; r < 16; r++) {
        const int t = w * 16 + r;
        const float* row = x2 + (t0 + t) * Cq;
        float v0 = row[lane], v1 = row[lane + 32], v2 = row[lane + 64];
        float s  = v0 + v1 + v2;
        float ss = v0 * v0 + v1 * v1 + v2 * v2;
        #pragma unroll
        for (int o = 16; o; o >>= 1) {
            s  += __shfl_xor_sync(0xffffffffu, s,  o);
            ss += __shfl_xor_sync(0xffffffffu, ss, o);
        }
        const float mu  = s * (1.0f / 96.0f);
        const float var = ss * (1.0f / 96.0f) - mu * mu;
        const float inv = rsqrtf(var + EPSq);
        __nv_bfloat16* arow = (__nv_bfloat16*)(smem + MS_A) + t * SA;
        arow[lane]      = __float2bfloat16((v0 - mu) * inv * g2[lane]      + b2[lane]);
        arow[lane + 32] = __float2bfloat16((v1 - mu) * inv * g2[lane + 32] + b2[lane + 32]);
        arow[lane + 64] = __float2bfloat16((v2 - mu) * inv * g2[lane + 64] + b2[lane + 64]);
    }
    __syncthreads();

    uint32_t afr[6][4];
    #pragma unroll
    for (int k = 0; k < 6; k++) {
        const uint32_t addr = sb + MS_A +
            (uint32_t)(((mrow0 + (lane & 15)) * SA + k * 16 + ((lane >> 4) << 3)) * 2);
        ldm4(afr[k], addr);
    }

    const int g = lane >> 2, tq = lane & 3;
    float ofr[6][2][4];
    #pragma unroll
    for (int i = 0; i < 6; i++)
        #pragma unroll
        for (int j = 0; j < 2; j++)
            #pragma unroll
            for (int q = 0; q < 4; q++) ofr[i][j][q] = 0.f;

    for (int chunk = 0; chunk < 3; chunk++) {
        for (int idx = tid; idx < 128 * 48; idx += 256) {
            const int row = idx / 48, cp = (idx - row * 48) * 2;
            const float2 v = *(const float2*)(fc1_w + (size_t)(chunk * 128 + row) * 96 + cp);
            *(uint32_t*)(smem + MS_B + (row * SB1 + cp) * 2) = packbf(v.x, v.y);
        }
        __syncthreads();

        #pragma unroll
        for (int nt2 = 0; nt2 < 8; nt2++) {
            const int n0 = nt2 * 16;
            float c0[4] = {0.f, 0.f, 0.f, 0.f}, c1[4] = {0.f, 0.f, 0.f, 0.f};
            #pragma unroll
            for (int k = 0; k < 6; k++) {
                uint32_t bfr[4];
                const uint32_t addr = sb + MS_B +
                    (uint32_t)(((n0 + (lane & 7) + ((lane & 16) ? 8 : 0)) * SB1
                               + k * 16 + ((lane & 8) ? 8 : 0)) * 2);
                ldm4(bfr, addr);
                mma_bf16(c0, afr[k], bfr);
                mma_bf16(c1, afr[k], bfr + 2);
            }
            #pragma unroll
            for (int tile = 0; tile < 2; tile++) {
                float* c = tile ? c1 : c0;
                const int nn = n0 + tile * 8 + 2 * tq;
                const float bb0 = fc1_b[chunk * 128 + nn];
                const float bb1 = fc1_b[chunk * 128 + nn + 1];
                *(uint32_t*)(smem + MS_H + ((mrow0 + g) * SH + nn) * 2) =
                    packbf(gelu_f(c[0] + bb0), gelu_f(c[1] + bb1));
                *(uint32_t*)(smem + MS_H + ((mrow0 + g + 8) * SH + nn) * 2) =
                    packbf(gelu_f(c[2] + bb0), gelu_f(c[3] + bb1));
            }
        }
        __syncthreads();

        for (int idx = tid; idx < 96 * 64; idx += 256) {
            const int row = idx >> 6, cp = (idx & 63) * 2;
            const float2 v = *(const float2*)(fc2_w + (size_t)row * MLPH + chunk * 128 + cp);
            *(uint32_t*)(smem + MS_B + (row * SB2 + cp) * 2) = packbf(v.x, v.y);
        }
        __syncthreads();

        uint32_t hfr[8][4];
        #pragma unroll
        for (int k = 0; k < 8; k++) {
            const uint32_t addr = sb + MS_H +
                (uint32_t)(((mrow0 + (lane & 15)) * SH + k * 16 + ((lane >> 4) << 3)) * 2);
            ldm4(hfr[k], addr);
        }
        #pragma unroll
        for (int nt2 = 0; nt2 < 6; nt2++) {
            const int n0 = nt2 * 16;
            #pragma unroll
            for (int k = 0; k < 8; k++) {
                uint32_t bfr[4];
                const uint32_t addr = sb + MS_B +
                    (uint32_t)(((n0 + (lane & 7) + ((lane & 16) ? 8 : 0)) * SB2
                               + k * 16 + ((lane & 8) ? 8 : 0)) * 2);
                ldm4(bfr, addr);
                mma_bf16(ofr[nt2][0], hfr[k], bfr);
                mma_bf16(ofr[nt2][1], hfr[k], bfr + 2);
            }
        }
        __syncthreads();
    }

    {
        const size_t rA = t0 + mrow0 + g;
        const size_t rB = rA + 8;
        const float* xA = x2 + rA * Cq;
        const float* xB = x2 + rB * Cq;
        float* oA = out + rA * Cq;
        float* oB = out + rB * Cq;
        #pragma unroll
        for (int nt2 = 0; nt2 < 6; nt2++) {
            #pragma unroll
            for (int tile = 0; tile < 2; tile++) {
                const int n = nt2 * 16 + tile * 8 + 2 * tq;
                const float* c = ofr[nt2][tile];
                const float b0 = fc2_b[n], b1 = fc2_b[n + 1];
                *(float2*)(oA + n) = make_float2(xA[n] + c[0] + b0, xA[n + 1] + c[1] + b1);
                *(float2*)(oB + n) = make_float2(xB[n] + c[2] + b0, xB[n + 1] + c[3] + b1);
            }
        }
    }
}

// ================= launch =================
extern "C" void kernel_launch(void* const* d_in, const int* in_sizes, int n_in,
                              void* d_out, int out_size)
{
    const float* x        = (const float*)d_in[0];
    const float* g1       = (const float*)d_in[1];
    const float* b1       = (const float*)d_in[2];
    const float* qkv_w    = (const float*)d_in[3];
    const float* qkv_b    = (const float*)d_in[4];
    const float* rpb      = (const float*)d_in[5];
    const float* proj_w   = (const float*)d_in[6];
    const float* proj_b   = (const float*)d_in[7];
    const float* g2       = (const float*)d_in[8];
    const float* b2       = (const float*)d_in[9];
    const float* fc1_w    = (const float*)d_in[10];
    const float* fc1_b    = (const float*)d_in[11];
    const float* fc2_w    = (const float*)d_in[12];
    const float* fc2_b    = (const float*)d_in[13];
    const float* attn_mask= (const float*)d_in[14];
    const int*   rel_index= (const int*)  d_in[15];
    float* out = (float*)d_out;

    cudaFuncSetAttribute(swin_attn_mma, cudaFuncAttributeMaxDynamicSharedMemorySize, AS_TOTAL);
    cudaFuncSetAttribute(swin_mlp_mma,  cudaFuncAttributeMaxDynamicSharedMemorySize, MS_TOTAL);

    float* x2;
    cudaGetSymbolAddress((void**)&x2, g_x2);

    prep_bias_kernel<<<48, 256>>>(rpb, rel_index);
    swin_attn_mma<<<TOKENS / 128, 256, AS_TOTAL>>>(x, g1, b1, qkv_w, qkv_b,
                                                   proj_w, proj_b, attn_mask, x2);
    swin_mlp_mma<<<TOKENS / 128, 256, MS_TOTAL>>>(x2, g2, b2, fc1_w, fc1_b,
                                                  fc2_w, fc2_b, out);
}

// round 7
// speedup vs baseline: 6.3741x; 1.2423x over previous
#include <cuda_runtime.h>
#include <cuda_bf16.h>
#include <math.h>
#include <stdint.h>

// ---------------- static config ----------------
#define Bq   4
#define Cq   96
#define SSz  4
#define NHq  3
#define MLPH 384
#define TOKENS (Bq*256*256)

#define SCALEq 0.17677669529663687f
#define EPSq   1e-5f

// ---------------- precomputed bf16 tables ----------------
static __device__ __align__(16) __nv_bfloat16 g_bias[3 * 64 * 64];
static __device__ __align__(16) __nv_bfloat16 g_qkvw[288 * 96];
static __device__ __align__(16) __nv_bfloat16 g_projw[96 * 96];
static __device__ __align__(16) __nv_bfloat16 g_fc1w[384 * 96];
static __device__ __align__(16) __nv_bfloat16 g_fc2w[96 * 384];

// ---------------- warp-mma helpers ----------------
__device__ __forceinline__ uint32_t smem_u32(const void* p) {
    uint32_t a;
    asm("{ .reg .u64 t; cvta.to.shared.u64 t, %1; cvt.u32.u64 %0, t; }" : "=r"(a) : "l"(p));
    return a;
}
__device__ __forceinline__ void ldm4(uint32_t* r, uint32_t addr) {
    asm volatile("ldmatrix.sync.aligned.m8n8.x4.shared.b16 {%0,%1,%2,%3}, [%4];"
        : "=r"(r[0]), "=r"(r[1]), "=r"(r[2]), "=r"(r[3]) : "r"(addr));
}
__device__ __forceinline__ void mma_bf16(float* c, const uint32_t* a, const uint32_t* b) {
    asm volatile("mma.sync.aligned.m16n8k16.row.col.f32.bf16.bf16.f32 "
        "{%0,%1,%2,%3}, {%4,%5,%6,%7}, {%8,%9}, {%0,%1,%2,%3};"
        : "+f"(c[0]), "+f"(c[1]), "+f"(c[2]), "+f"(c[3])
        : "r"(a[0]), "r"(a[1]), "r"(a[2]), "r"(a[3]), "r"(b[0]), "r"(b[1]));
}
__device__ __forceinline__ float gelu_f(float v) {
    return 0.5f * v * (1.0f + erff(v * 0.70710678118654752f));
}
__device__ __forceinline__ uint32_t packbf(float a, float b) {
    const __nv_bfloat162 h = __floats2bfloat162_rn(a, b);
    return *(const uint32_t*)&h;
}
__device__ __forceinline__ float2 unpackbf(uint32_t u) {
    const __nv_bfloat162 h = *(const __nv_bfloat162*)&u;
    return make_float2(__bfloat162float(h.x), __bfloat162float(h.y));
}

// ================= prep: bias gather + weight bf16 conversion =================
__global__ void prep_kernel(const float* __restrict__ rpb, const int* __restrict__ rel_index,
                            const float* __restrict__ qkv_w, const float* __restrict__ proj_w,
                            const float* __restrict__ fc1_w, const float* __restrict__ fc2_w)
{
    const int idx = blockIdx.x * 256 + threadIdx.x;   // 144*256 = 36864
    if (idx < 3 * 4096) {
        const int hh = idx >> 12, ij = idx & 4095;
        g_bias[hh * 4096 + ij] = __float2bfloat16(rpb[rel_index[ij] * 3 + hh]);
    }
    if (idx < 288 * 96) g_qkvw[idx] = __float2bfloat16(qkv_w[idx]);
    if (idx < 96 * 96)  g_projw[idx] = __float2bfloat16(proj_w[idx]);
    if (idx < 384 * 96) {
        g_fc1w[idx] = __float2bfloat16(fc1_w[idx]);
        g_fc2w[idx] = __float2bfloat16(fc2_w[idx]);
    }
}

// ---------------- fused smem layout (bytes) ----------------
#define SAT 104     // a_s / k_s / B1 row stride (bf16) -> 208 B
#define SVT 136     // vt_s / B2 / H row stride (bf16)  -> 272 B
#define AS_A  0                      // [128][104] bf16: LN1 -> O -> LN2'd MLP A
#define AS_K  26624                  // [128][104]: K -> MLP B1/B2 staging
#define AS_VT 53248                  // [96][136]: v^T -> MLP H1 [128][136] (extends into AS_W)
#define AS_W  79360                  // [96][104]: weight chunk (qkv/proj)
#define AS_TOTAL 99328

// ================= fused block kernel: 2 windows (128 tokens) per CTA =========
__global__ __launch_bounds__(256, 2)
void swin_block_fused(const float* __restrict__ x,
                      const float* __restrict__ g1, const float* __restrict__ b1,
                      const float* __restrict__ qkv_b, const float* __restrict__ proj_b,
                      const float* __restrict__ g2, const float* __restrict__ b2,
                      const float* __restrict__ fc1_b, const float* __restrict__ fc2_b,
                      const float* __restrict__ attn_mask,
                      float* __restrict__ out)
{
    extern __shared__ __align__(16) char smem[];
    const uint32_t sb = smem_u32(smem);
    const int tid = threadIdx.x, lane = tid & 31, warp = tid >> 5;

    const int wglob = blockIdx.x * 2 + (warp >> 2);
    const int b     = wglob >> 10;
    const int wrem  = wglob & 1023;
    const int wy    = wrem >> 5, wx = wrem & 31;
    const int wl    = warp >> 2;
    const int mrow0 = warp * 16;

    // ---- LN1 + gather -> a_s bf16 [128][104] ----
    #pragma unroll
    for (int r = 0; r < 16; r++) {
        const int t = mrow0 + r;
        const int i = t & 63;
        const int yy = (wy * 8 + (i >> 3) + SSz) & 255;
        const int xx = (wx * 8 + (i & 7) + SSz) & 255;
        const float* row = x + (size_t)(b * 65536 + yy * 256 + xx) * Cq;
        float v0 = row[lane], v1 = row[lane + 32], v2 = row[lane + 64];
        float s  = v0 + v1 + v2;
        float ss = v0 * v0 + v1 * v1 + v2 * v2;
        #pragma unroll
        for (int o = 16; o; o >>= 1) {
            s  += __shfl_xor_sync(0xffffffffu, s,  o);
            ss += __shfl_xor_sync(0xffffffffu, ss, o);
        }
        const float mu  = s * (1.0f / 96.0f);
        const float var = ss * (1.0f / 96.0f) - mu * mu;
        const float inv = rsqrtf(var + EPSq);
        __nv_bfloat16* arow = (__nv_bfloat16*)(smem + AS_A) + t * SAT;
        arow[lane]      = __float2bfloat16((v0 - mu) * inv * g1[lane]      + b1[lane]);
        arow[lane + 32] = __float2bfloat16((v1 - mu) * inv * g1[lane + 32] + b1[lane + 32]);
        arow[lane + 64] = __float2bfloat16((v2 - mu) * inv * g1[lane + 64] + b1[lane + 64]);
    }
    __syncthreads();

    // ---- A fragments (reused across all 3 qkv chunks) ----
    uint32_t afr[6][4];
    #pragma unroll
    for (int k = 0; k < 6; k++)
        ldm4(afr[k], sb + AS_A + (uint32_t)(((mrow0 + (lane & 15)) * SAT + k * 16 + ((lane >> 4) << 3)) * 2));

    const int g = lane >> 2, tq = lane & 3;

    // ---- QKV (Q->regs, K->smem, V^T->smem) ----
    uint32_t qafr[6][4];
    #pragma unroll
    for (int chunk = 0; chunk < 3; chunk++) {
        for (int idx = tid; idx < 1152; idx += 256) {
            const int row = idx / 12, q = idx % 12;
            *(uint4*)(smem + AS_W + row * 208 + q * 16) =
                *(const uint4*)((const char*)g_qkvw + chunk * 18432 + row * 192 + q * 16);
        }
        __syncthreads();

        #pragma unroll
        for (int nt2 = 0; nt2 < 6; nt2++) {
            float c0[4] = {0.f,0.f,0.f,0.f}, c1[4] = {0.f,0.f,0.f,0.f};
            #pragma unroll
            for (int kt = 0; kt < 6; kt++) {
                uint32_t bfr[4];
                ldm4(bfr, sb + AS_W + (uint32_t)(((nt2 * 16 + (lane & 7) + ((lane & 16) ? 8 : 0)) * SAT
                                                 + kt * 16 + ((lane & 8) ? 8 : 0)) * 2));
                mma_bf16(c0, afr[kt], bfr);
                mma_bf16(c1, afr[kt], bfr + 2);
            }
            const int n = nt2 * 16 + 2 * tq;
            if (chunk == 0) {
                const float b0 = qkv_b[n],     b1v = qkv_b[n + 1];
                const float b8 = qkv_b[n + 8], b9  = qkv_b[n + 9];
                qafr[nt2][0] = packbf((c0[0] + b0) * SCALEq, (c0[1] + b1v) * SCALEq);
                qafr[nt2][1] = packbf((c0[2] + b0) * SCALEq, (c0[3] + b1v) * SCALEq);
                qafr[nt2][2] = packbf((c1[0] + b8) * SCALEq, (c1[1] + b9) * SCALEq);
                qafr[nt2][3] = packbf((c1[2] + b8) * SCALEq, (c1[3] + b9) * SCALEq);
            } else if (chunk == 1) {
                const float b0 = qkv_b[96 + n],     b1v = qkv_b[96 + n + 1];
                const float b8 = qkv_b[96 + n + 8], b9  = qkv_b[96 + n + 9];
                *(uint32_t*)(smem + AS_K + (((mrow0 + g)     * SAT) + n)     * 2) = packbf(c0[0] + b0, c0[1] + b1v);
                *(uint32_t*)(smem + AS_K + (((mrow0 + g + 8) * SAT) + n)     * 2) = packbf(c0[2] + b0, c0[3] + b1v);
                *(uint32_t*)(smem + AS_K + (((mrow0 + g)     * SAT) + n + 8) * 2) = packbf(c1[0] + b8, c1[1] + b9);
                *(uint32_t*)(smem + AS_K + (((mrow0 + g + 8) * SAT) + n + 8) * 2) = packbf(c1[2] + b8, c1[3] + b9);
            } else {
                const float b0 = qkv_b[192 + n],     b1v = qkv_b[192 + n + 1];
                const float b8 = qkv_b[192 + n + 8], b9  = qkv_b[192 + n + 9];
                const int cc = wl * 64 + (warp & 3) * 16 + g;
                __nv_bfloat16* vt = (__nv_bfloat16*)(smem + AS_VT);
                vt[(n)     * SVT + cc]     = __float2bfloat16(c0[0] + b0);
                vt[(n + 1) * SVT + cc]     = __float2bfloat16(c0[1] + b1v);
                vt[(n)     * SVT + cc + 8] = __float2bfloat16(c0[2] + b0);
                vt[(n + 1) * SVT + cc + 8] = __float2bfloat16(c0[3] + b1v);
                vt[(n + 8) * SVT + cc]     = __float2bfloat16(c1[0] + b8);
                vt[(n + 9) * SVT + cc]     = __float2bfloat16(c1[1] + b9);
                vt[(n + 8) * SVT + cc + 8] = __float2bfloat16(c1[2] + b8);
                vt[(n + 9) * SVT + cc + 8] = __float2bfloat16(c1[3] + b9);
            }
        }
        __syncthreads();
    }

    // ---- mask preload ----
    const int i0 = (warp & 3) * 16;
    uint32_t mreg[16];
    {
        const float* mbase = attn_mask + (size_t)wrem * 4096;
        #pragma unroll
        for (int nt2 = 0; nt2 < 4; nt2++)
            #pragma unroll
            for (int t2 = 0; t2 < 2; t2++) {
                const int col = nt2 * 16 + t2 * 8 + 2 * tq;
                const int id = (nt2 * 2 + t2) * 2;
                mreg[id]     = packbf(mbase[(i0 + g) * 64 + col],     mbase[(i0 + g) * 64 + col + 1]);
                mreg[id + 1] = packbf(mbase[(i0 + g + 8) * 64 + col], mbase[(i0 + g + 8) * 64 + col + 1]);
            }
    }

    // ---- per-head attention ----
    for (int hh = 0; hh < NHq; hh++) {
        float sc[4][8];
        #pragma unroll
        for (int nt2 = 0; nt2 < 4; nt2++) {
            #pragma unroll
            for (int q = 0; q < 8; q++) sc[nt2][q] = 0.f;
            #pragma unroll
            for (int kt2 = 0; kt2 < 2; kt2++) {
                uint32_t bfr[4];
                ldm4(bfr, sb + AS_K + (uint32_t)(((wl * 64 + nt2 * 16 + (lane & 7) + ((lane & 16) ? 8 : 0)) * SAT
                                                 + hh * 32 + kt2 * 16 + ((lane & 8) ? 8 : 0)) * 2));
                mma_bf16(sc[nt2],     qafr[2 * hh + kt2], bfr);
                mma_bf16(sc[nt2] + 4, qafr[2 * hh + kt2], bfr + 2);
            }
        }
        const __nv_bfloat16* bias_h = g_bias + hh * 4096;
        #pragma unroll
        for (int nt2 = 0; nt2 < 4; nt2++)
            #pragma unroll
            for (int t2 = 0; t2 < 2; t2++) {
                const int col = nt2 * 16 + t2 * 8 + 2 * tq;
                #pragma unroll
                for (int rs = 0; rs < 2; rs++) {
                    float* cp = &sc[nt2][t2 * 4 + rs * 2];
                    const float2 bv = unpackbf(*(const uint32_t*)(bias_h + (i0 + g + rs * 8) * 64 + col));
                    const float2 mv = unpackbf(mreg[(nt2 * 2 + t2) * 2 + rs]);
                    cp[0] += bv.x + mv.x;
                    cp[1] += bv.y + mv.y;
                }
            }
        float mx0 = -1e30f, mx1 = -1e30f;
        #pragma unroll
        for (int nt2 = 0; nt2 < 4; nt2++)
            #pragma unroll
            for (int t2 = 0; t2 < 2; t2++) {
                mx0 = fmaxf(mx0, fmaxf(sc[nt2][t2 * 4],     sc[nt2][t2 * 4 + 1]));
                mx1 = fmaxf(mx1, fmaxf(sc[nt2][t2 * 4 + 2], sc[nt2][t2 * 4 + 3]));
            }
        mx0 = fmaxf(mx0, __shfl_xor_sync(0xffffffffu, mx0, 1));
        mx0 = fmaxf(mx0, __shfl_xor_sync(0xffffffffu, mx0, 2));
        mx1 = fmaxf(mx1, __shfl_xor_sync(0xffffffffu, mx1, 1));
        mx1 = fmaxf(mx1, __shfl_xor_sync(0xffffffffu, mx1, 2));
        float s0 = 0.f, s1 = 0.f;
        #pragma unroll
        for (int nt2 = 0; nt2 < 4; nt2++)
            #pragma unroll
            for (int t2 = 0; t2 < 2; t2++) {
                float* cp = &sc[nt2][t2 * 4];
                cp[0] = __expf(cp[0] - mx0); cp[1] = __expf(cp[1] - mx0);
                cp[2] = __expf(cp[2] - mx1); cp[3] = __expf(cp[3] - mx1);
                s0 += cp[0] + cp[1];
                s1 += cp[2] + cp[3];
            }
        s0 += __shfl_xor_sync(0xffffffffu, s0, 1);
        s0 += __shfl_xor_sync(0xffffffffu, s0, 2);
        s1 += __shfl_xor_sync(0xffffffffu, s1, 1);
        s1 += __shfl_xor_sync(0xffffffffu, s1, 2);
        const float inv0 = 1.0f / s0, inv1 = 1.0f / s1;
        uint32_t pa[4][4];
        #pragma unroll
        for (int kt = 0; kt < 4; kt++) {
            pa[kt][0] = packbf(sc[kt][0] * inv0, sc[kt][1] * inv0);
            pa[kt][1] = packbf(sc[kt][2] * inv1, sc[kt][3] * inv1);
            pa[kt][2] = packbf(sc[kt][4] * inv0, sc[kt][5] * inv0);
            pa[kt][3] = packbf(sc[kt][6] * inv1, sc[kt][7] * inv1);
        }
        #pragma unroll
        for (int nb = 0; nb < 2; nb++) {
            float oc0[4] = {0.f,0.f,0.f,0.f}, oc1[4] = {0.f,0.f,0.f,0.f};
            #pragma unroll
            for (int kt = 0; kt < 4; kt++) {
                uint32_t bfr[4];
                ldm4(bfr, sb + AS_VT + (uint32_t)(((hh * 32 + nb * 16 + (lane & 7) + ((lane & 16) ? 8 : 0)) * SVT
                                                  + wl * 64 + kt * 16 + ((lane & 8) ? 8 : 0)) * 2));
                mma_bf16(oc0, pa[kt], bfr);
                mma_bf16(oc1, pa[kt], bfr + 2);
            }
            const int col = hh * 32 + nb * 16 + 2 * tq;
            *(uint32_t*)(smem + AS_A + (((mrow0 + g)     * SAT) + col)     * 2) = packbf(oc0[0], oc0[1]);
            *(uint32_t*)(smem + AS_A + (((mrow0 + g + 8) * SAT) + col)     * 2) = packbf(oc0[2], oc0[3]);
            *(uint32_t*)(smem + AS_A + (((mrow0 + g)     * SAT) + col + 8) * 2) = packbf(oc1[0], oc1[1]);
            *(uint32_t*)(smem + AS_A + (((mrow0 + g + 8) * SAT) + col + 8) * 2) = packbf(oc1[2], oc1[3]);
        }
    }
    __syncthreads();

    // ---- stage proj_w -> AS_W and fc1_w chunk0 -> AS_K ----
    for (int idx = tid; idx < 1152; idx += 256) {
        const int row = idx / 12, q = idx % 12;
        *(uint4*)(smem + AS_W + row * 208 + q * 16) =
            *(const uint4*)((const char*)g_projw + row * 192 + q * 16);
    }
    for (int idx = tid; idx < 1536; idx += 256) {
        const int row = idx / 12, q = idx % 12;
        *(uint4*)(smem + AS_K + row * 208 + q * 16) =
            *(const uint4*)((const char*)g_fc1w + row * 192 + q * 16);
    }
    __syncthreads();

    // ---- residual base addresses ----
    size_t baseA, baseB;
    {
        const int tA = mrow0 + g, tB = tA + 8;
        const int iA = tA & 63, iB = tB & 63;
        const int yyA = (wy * 8 + (iA >> 3) + SSz) & 255, xxA = (wx * 8 + (iA & 7) + SSz) & 255;
        const int yyB = (wy * 8 + (iB >> 3) + SSz) & 255, xxB = (wx * 8 + (iB & 7) + SSz) & 255;
        baseA = ((size_t)(b * 65536 + yyA * 256 + xxA)) * Cq;
        baseB = ((size_t)(b * 65536 + yyB * 256 + xxB)) * Cq;
    }

    // ---- proj mma: x2 stays in registers ----
    float x2v[6][2][4];
    {
        uint32_t ofr2[6][4];
        #pragma unroll
        for (int k = 0; k < 6; k++)
            ldm4(ofr2[k], sb + AS_A + (uint32_t)(((mrow0 + (lane & 15)) * SAT + k * 16 + ((lane >> 4) << 3)) * 2));

        #pragma unroll
        for (int nt2 = 0; nt2 < 6; nt2++) {
            float c0[4] = {0.f,0.f,0.f,0.f}, c1[4] = {0.f,0.f,0.f,0.f};
            #pragma unroll
            for (int kt = 0; kt < 6; kt++) {
                uint32_t bfr[4];
                ldm4(bfr, sb + AS_W + (uint32_t)(((nt2 * 16 + (lane & 7) + ((lane & 16) ? 8 : 0)) * SAT
                                                 + kt * 16 + ((lane & 8) ? 8 : 0)) * 2));
                mma_bf16(c0, ofr2[kt], bfr);
                mma_bf16(c1, ofr2[kt], bfr + 2);
            }
            const int n = nt2 * 16 + 2 * tq;
            {
                const float b0 = proj_b[n], b1v = proj_b[n + 1];
                const float2 xA = *(const float2*)(x + baseA + n);
                const float2 xB = *(const float2*)(x + baseB + n);
                x2v[nt2][0][0] = xA.x + c0[0] + b0;  x2v[nt2][0][1] = xA.y + c0[1] + b1v;
                x2v[nt2][0][2] = xB.x + c0[2] + b0;  x2v[nt2][0][3] = xB.y + c0[3] + b1v;
            }
            {
                const float b0 = proj_b[n + 8], b1v = proj_b[n + 9];
                const float2 xA = *(const float2*)(x + baseA + n + 8);
                const float2 xB = *(const float2*)(x + baseB + n + 8);
                x2v[nt2][1][0] = xA.x + c1[0] + b0;  x2v[nt2][1][1] = xA.y + c1[1] + b1v;
                x2v[nt2][1][2] = xB.x + c1[2] + b0;  x2v[nt2][1][3] = xB.y + c1[3] + b1v;
            }
        }
    }

    // ---- LN2 in registers (quad reductions) -> A bf16 ----
    {
        float s0 = 0.f, ss0 = 0.f, s1 = 0.f, ss1 = 0.f;
        #pragma unroll
        for (int nt2 = 0; nt2 < 6; nt2++)
            #pragma unroll
            for (int tl = 0; tl < 2; tl++) {
                const float a0 = x2v[nt2][tl][0], a1 = x2v[nt2][tl][1];
                const float a2 = x2v[nt2][tl][2], a3 = x2v[nt2][tl][3];
                s0 += a0 + a1;  ss0 += a0 * a0 + a1 * a1;
                s1 += a2 + a3;  ss1 += a2 * a2 + a3 * a3;
            }
        s0  += __shfl_xor_sync(0xffffffffu, s0, 1);  s0  += __shfl_xor_sync(0xffffffffu, s0, 2);
        ss0 += __shfl_xor_sync(0xffffffffu, ss0, 1); ss0 += __shfl_xor_sync(0xffffffffu, ss0, 2);
        s1  += __shfl_xor_sync(0xffffffffu, s1, 1);  s1  += __shfl_xor_sync(0xffffffffu, s1, 2);
        ss1 += __shfl_xor_sync(0xffffffffu, ss1, 1); ss1 += __shfl_xor_sync(0xffffffffu, ss1, 2);
        const float mu0 = s0 * (1.0f / 96.0f);
        const float iv0 = rsqrtf(ss0 * (1.0f / 96.0f) - mu0 * mu0 + EPSq);
        const float mu1 = s1 * (1.0f / 96.0f);
        const float iv1 = rsqrtf(ss1 * (1.0f / 96.0f) - mu1 * mu1 + EPSq);
        #pragma unroll
        for (int nt2 = 0; nt2 < 6; nt2++)
            #pragma unroll
            for (int tl = 0; tl < 2; tl++) {
                const int n = nt2 * 16 + tl * 8 + 2 * tq;
                const float ga = g2[n], gb = g2[n + 1], ba = b2[n], bb = b2[n + 1];
                *(uint32_t*)(smem + AS_A + (((mrow0 + g) * SAT) + n) * 2) =
                    packbf((x2v[nt2][tl][0] - mu0) * iv0 * ga + ba,
                           (x2v[nt2][tl][1] - mu0) * iv0 * gb + bb);
                *(uint32_t*)(smem + AS_A + (((mrow0 + g + 8) * SAT) + n) * 2) =
                    packbf((x2v[nt2][tl][2] - mu1) * iv1 * ga + ba,
                           (x2v[nt2][tl][3] - mu1) * iv1 * gb + bb);
            }
    }
    __syncthreads();   // proj_w dead; B1 chunk0 visible; H region free

    // ---- MLP ----
    uint32_t mafr[6][4];
    #pragma unroll
    for (int k = 0; k < 6; k++)
        ldm4(mafr[k], sb + AS_A + (uint32_t)(((mrow0 + (lane & 15)) * SAT + k * 16 + ((lane >> 4) << 3)) * 2));

    float ofr[6][2][4];
    #pragma unroll
    for (int i = 0; i < 6; i++)
        #pragma unroll
        for (int j = 0; j < 2; j++)
            #pragma unroll
            for (int q = 0; q < 4; q++) ofr[i][j][q] = 0.f;

    for (int chunk = 0; chunk < 3; chunk++) {
        if (chunk > 0) {
            __syncthreads();   // all warps done with previous B2
            for (int idx = tid; idx < 1536; idx += 256) {
                const int row = idx / 12, q = idx % 12;
                *(uint4*)(smem + AS_K + row * 208 + q * 16) =
                    *(const uint4*)((const char*)g_fc1w + chunk * 24576 + row * 192 + q * 16);
            }
            __syncthreads();
        }

        // FC1 + GELU -> H (own rows)
        #pragma unroll
        for (int nt2 = 0; nt2 < 8; nt2++) {
            const int n0 = nt2 * 16;
            float c0[4] = {0.f,0.f,0.f,0.f}, c1[4] = {0.f,0.f,0.f,0.f};
            #pragma unroll
            for (int k = 0; k < 6; k++) {
                uint32_t bfr[4];
                ldm4(bfr, sb + AS_K + (uint32_t)(((n0 + (lane & 7) + ((lane & 16) ? 8 : 0)) * SAT
                                                 + k * 16 + ((lane & 8) ? 8 : 0)) * 2));
                mma_bf16(c0, mafr[k], bfr);
                mma_bf16(c1, mafr[k], bfr + 2);
            }
            #pragma unroll
            for (int tl = 0; tl < 2; tl++) {
                float* c = tl ? c1 : c0;
                const int nn = n0 + tl * 8 + 2 * tq;
                const float bb0 = fc1_b[chunk * 128 + nn];
                const float bb1 = fc1_b[chunk * 128 + nn + 1];
                *(uint32_t*)(smem + AS_VT + ((mrow0 + g) * SVT + nn) * 2) =
                    packbf(gelu_f(c[0] + bb0), gelu_f(c[1] + bb1));
                *(uint32_t*)(smem + AS_VT + ((mrow0 + g + 8) * SVT + nn) * 2) =
                    packbf(gelu_f(c[2] + bb0), gelu_f(c[3] + bb1));
            }
        }
        __syncthreads();   // all warps done with B1

        // stage B2 chunk
        for (int idx = tid; idx < 1536; idx += 256) {
            const int row = idx / 16, q = idx % 16;
            *(uint4*)(smem + AS_K + row * 272 + q * 16) =
                *(const uint4*)((const char*)g_fc2w + row * 768 + chunk * 256 + q * 16);
        }
        __syncthreads();

        // FC2 accumulate
        #pragma unroll
        for (int k = 0; k < 8; k++) {
            uint32_t hfr[4];
            ldm4(hfr, sb + AS_VT + (uint32_t)(((mrow0 + (lane & 15)) * SVT + k * 16 + ((lane >> 4) << 3)) * 2));
            #pragma unroll
            for (int nt2 = 0; nt2 < 6; nt2++) {
                uint32_t bfr[4];
                ldm4(bfr, sb + AS_K + (uint32_t)(((nt2 * 16 + (lane & 7) + ((lane & 16) ? 8 : 0)) * SVT
                                                 + k * 16 + ((lane & 8) ? 8 : 0)) * 2));
                mma_bf16(ofr[nt2][0], hfr, bfr);
                mma_bf16(ofr[nt2][1], hfr, bfr + 2);
            }
        }
    }

    // ---- epilogue: out = x2 + mlp + fc2_b (scattered) ----
    #pragma unroll
    for (int nt2 = 0; nt2 < 6; nt2++) {
        #pragma unroll
        for (int tl = 0; tl < 2; tl++) {
            const int n = nt2 * 16 + tl * 8 + 2 * tq;
            const float b0 = fc2_b[n], b1v = fc2_b[n + 1];
            const float* c = ofr[nt2][tl];
            *(float2*)(out + baseA + n) = make_float2(x2v[nt2][tl][0] + c[0] + b0,
                                                      x2v[nt2][tl][1] + c[1] + b1v);
            *(float2*)(out + baseB + n) = make_float2(x2v[nt2][tl][2] + c[2] + b0,
                                                      x2v[nt2][tl][3] + c[3] + b1v);
        }
    }
}

// ================= launch =================
extern "C" void kernel_launch(void* const* d_in, const int* in_sizes, int n_in,
                              void* d_out, int out_size)
{
    const float* x        = (const float*)d_in[0];
    const float* g1       = (const float*)d_in[1];
    const float* b1       = (const float*)d_in[2];
    const float* qkv_w    = (const float*)d_in[3];
    const float* qkv_b    = (const float*)d_in[4];
    const float* rpb      = (const float*)d_in[5];
    const float* proj_w   = (const float*)d_in[6];
    const float* proj_b   = (const float*)d_in[7];
    const float* g2       = (const float*)d_in[8];
    const float* b2       = (const float*)d_in[9];
    const float* fc1_w    = (const float*)d_in[10];
    const float* fc1_b    = (const float*)d_in[11];
    const float* fc2_w    = (const float*)d_in[12];
    const float* fc2_b    = (const float*)d_in[13];
    const float* attn_mask= (const float*)d_in[14];
    const int*   rel_index= (const int*)  d_in[15];
    float* out = (float*)d_out;

    cudaFuncSetAttribute(swin_block_fused, cudaFuncAttributeMaxDynamicSharedMemorySize, AS_TOTAL);

    prep_kernel<<<144, 256>>>(rpb, rel_index, qkv_w, proj_w, fc1_w, fc2_w);
    swin_block_fused<<<TOKENS / 128, 256, AS_TOTAL>>>(x, g1, b1, qkv_b, proj_b,
                                                      g2, b2, fc1_b, fc2_b,
                                                      attn_mask, out);
}